// round 9
// baseline (speedup 1.0000x reference)
#include <cuda_runtime.h>

#define B_    4
#define CDIM  96
#define L_    9216
#define DM    192
#define NS    16
#define RT    6
#define BL    (B_*L_)
#define TT    128
#define NTILE (BL/TT)     /* 288 */
#define G_    96
#define NCH   (L_/G_)     /* 96 */
#define TTP   132

/* ---- scratch ---- */
__device__ float g_xin[(size_t)B_*DM*L_];
__device__ float g_xc [(size_t)B_*DM*L_];
__device__ float g_kp [(size_t)B_*DM*L_];
__device__ float g_qp [(size_t)B_*DM*L_];
__device__ float g_dl [(size_t)B_*DM*L_];
__device__ float g_z  [(size_t)B_*DM*L_];
__device__ float g_Bs [(size_t)B_*NS*L_];
__device__ float g_Cs [(size_t)B_*NS*L_];
__device__ float g_y  [(size_t)B_*DM*L_];
__device__ float g_P  [(size_t)B_*NCH*DM*NS];
__device__ float g_Hl [(size_t)B_*NCH*DM*NS];
__device__ float g_Hi [(size_t)B_*NCH*DM*NS];

__device__ __forceinline__ float siluf(float v) { return v / (1.0f + __expf(-v)); }

/* 16 FMAs: one float4 weight vector vs 4 float4 x vectors into acc[4][j] */
#define FMA_GROUP16(j)                                                   \
    {   float4 wq = *(const float4*)&wrow[kk];                           \
        acc[0][j] = fmaf(wq.x, xq[0].x, acc[0][j]);                      \
        acc[1][j] = fmaf(wq.x, xq[0].y, acc[1][j]);                      \
        acc[2][j] = fmaf(wq.x, xq[0].z, acc[2][j]);                      \
        acc[3][j] = fmaf(wq.x, xq[0].w, acc[3][j]);                      \
        acc[0][j] = fmaf(wq.y, xq[1].x, acc[0][j]);                      \
        acc[1][j] = fmaf(wq.y, xq[1].y, acc[1][j]);                      \
        acc[2][j] = fmaf(wq.y, xq[1].z, acc[2][j]);                      \
        acc[3][j] = fmaf(wq.y, xq[1].w, acc[3][j]);                      \
        acc[0][j] = fmaf(wq.z, xq[2].x, acc[0][j]);                      \
        acc[1][j] = fmaf(wq.z, xq[2].y, acc[1][j]);                      \
        acc[2][j] = fmaf(wq.z, xq[2].z, acc[2][j]);                      \
        acc[3][j] = fmaf(wq.z, xq[2].w, acc[3][j]);                      \
        acc[0][j] = fmaf(wq.w, xq[3].x, acc[0][j]);                      \
        acc[1][j] = fmaf(wq.w, xq[3].y, acc[1][j]);                      \
        acc[2][j] = fmaf(wq.w, xq[3].z, acc[2][j]);                      \
        acc[3][j] = fmaf(wq.w, xq[3].w, acc[3][j]); }

/* ==== fused 3x GEMM (in_proj / K / Q): K=96, N-half=96 per block ==== */
__global__ void __launch_bounds__(512, 2)
gemm3_k96(const float* __restrict__ x, const float* __restrict__ Kin,
          const float* __restrict__ Qin, const float* __restrict__ in_w,
          const float* __restrict__ k_w, const float* __restrict__ k_b,
          const float* __restrict__ k_ln_g, const float* __restrict__ k_ln_b,
          const float* __restrict__ q_w, const float* __restrict__ q_b,
          const float* __restrict__ q_ln_g, const float* __restrict__ q_ln_b)
{
    extern __shared__ float sm[];
    float* xs = sm;                      // 96*TTP
    float* ws = sm + 96*TTP;             // 96*96 (this block's N-half)
    float* mean_s = ws + 96*96;          // 128
    float* rstd_s = mean_s + 128;        // 128

    int sel = blockIdx.y;
    int c0  = blockIdx.z * 96;           // N-half offset
    const float* src  = (sel==0) ? x    : (sel==1 ? Kin : Qin);
    const float* W    = (sel==0) ? in_w : (sel==1 ? k_w : q_w);
    const float* bias = (sel==0) ? 0    : (sel==1 ? k_b : q_b);
    const float* lng  = (sel==1) ? k_ln_g : q_ln_g;
    const float* lnb  = (sel==1) ? k_ln_b : q_ln_b;

    int tid = threadIdx.x;
    int tok0 = blockIdx.x * TT;
    int b = tok0 / L_, l0 = tok0 % L_;
    const float* srcb = src + ((size_t)b*CDIM)*L_ + l0;

    for (int i = tid; i < 96*CDIM; i += 512) ws[i] = W[(size_t)c0*CDIM + i];
    for (int i = tid; i < CDIM*TT; i += 512) {
        int t = i % TT, k = i / TT;
        xs[k*TTP + t] = srcb[(size_t)k*L_ + t];
    }
    __syncthreads();

    if (sel != 0) {
        if (tid < TT) {
            float s = 0.f, ss = 0.f;
            for (int c = 0; c < CDIM; c++) { float v = xs[c*TTP + tid]; s += v; ss += v*v; }
            float m = s * (1.0f/CDIM);
            float var = ss * (1.0f/CDIM) - m*m;
            mean_s[tid] = m; rstd_s[tid] = rsqrtf(var + 1e-5f);
        }
        __syncthreads();
        for (int i = tid; i < CDIM*TT; i += 512) {
            int t = i % TT, c = i / TT;
            xs[c*TTP + t] = (xs[c*TTP + t] - mean_s[t]) * rstd_s[t] * lng[c] + lnb[c];
        }
        __syncthreads();
    }

    int tx = tid & 31, ty = tid >> 5;
    float acc[4][6];
    #pragma unroll
    for (int m = 0; m < 4; m++)
        #pragma unroll
        for (int j = 0; j < 6; j++) acc[m][j] = 0.f;

    #pragma unroll 2
    for (int kk = 0; kk < CDIM; kk += 4) {
        float4 xq[4];
        #pragma unroll
        for (int q = 0; q < 4; q++)
            xq[q] = *(const float4*)&xs[(kk+q)*TTP + tx*4];
        #pragma unroll
        for (int j = 0; j < 6; j++) {
            const float* wrow = &ws[(ty + 16*j)*CDIM];
            FMA_GROUP16(j)
        }
    }

    float* dst = (sel == 0) ? g_xin : ((sel == 1) ? g_kp : g_qp);
    float* dstb = dst + ((size_t)b*DM)*L_ + l0;
    #pragma unroll
    for (int j = 0; j < 6; j++) {
        int c = ty + 16*j;
        float bv = bias ? bias[c0 + c] : 0.f;
        float4 v;
        v.x = acc[0][j] + bv; v.y = acc[1][j] + bv;
        v.z = acc[2][j] + bv; v.w = acc[3][j] + bv;
        if (sel != 0) { v.x = siluf(v.x); v.y = siluf(v.y); v.z = siluf(v.z); v.w = siluf(v.w); }
        *(float4*)&dstb[(size_t)(c0 + c)*L_ + tx*4] = v;
    }
}

/* ============ depthwise causal conv (k=4) + silu ============ */
__global__ void __launch_bounds__(256)
conv_silu(const float* __restrict__ cw, const float* __restrict__ cb)
{
    int gid = blockIdx.x * blockDim.x + threadIdx.x;
    if (gid >= B_*DM*L_) return;
    int l  = gid % L_;
    int bd = gid / L_;
    int d  = bd % DM;
    const float* p = g_xin + (size_t)bd*L_ + l;
    float acc = cb[d] + cw[d*4+3] * p[0];
    if (l >= 1) acc = fmaf(cw[d*4+2], p[-1], acc);
    if (l >= 2) acc = fmaf(cw[d*4+1], p[-2], acc);
    if (l >= 3) acc = fmaf(cw[d*4+0], p[-3], acc);
    g_xc[gid] = siluf(acc);
}

/* ============ dtbc: x_dbl = cat(xc,kp) @ dtbc_w^T, then delta/B/C ============ */
__global__ void __launch_bounds__(512, 2)
dtbc_kernel(const float* __restrict__ dtbc_w, const float* __restrict__ dt_w,
            const float* __restrict__ dt_b)
{
    extern __shared__ float sm[];
    float* xs   = sm;                    // 96*TTP
    float* ws   = xs + 96*TTP;           // 38*96
    float* dbl  = ws + 38*96;            // 38*TTP
    float* dtw  = dbl + 38*TTP;          // 192*6
    float* dtb  = dtw + 192*6;           // 192
    int tid = threadIdx.x;
    int tok0 = blockIdx.x * TT;
    int b = tok0 / L_, l0 = tok0 % L_;

    for (int i = tid; i < DM*RT; i += 512) dtw[i] = dt_w[i];
    for (int i = tid; i < DM;    i += 512) dtb[i] = dt_b[i];

    int tx = tid & 31, ty = tid >> 5;
    float acc[4][3];
    #pragma unroll
    for (int m = 0; m < 4; m++)
        #pragma unroll
        for (int j = 0; j < 3; j++) acc[m][j] = 0.f;

    for (int kc = 0; kc < 4; kc++) {
        const float* src = (kc < 2) ? g_xc : g_kp;
        int k0 = (kc & 1) * 96;
        __syncthreads();
        for (int i = tid; i < 96*TT; i += 512) {
            int t = i % TT, k = i / TT;
            xs[k*TTP + t] = src[((size_t)b*DM + k0 + k)*L_ + l0 + t];
        }
        for (int i = tid; i < 38*96; i += 512) {
            int c = i / 96, kk = i % 96;
            ws[i] = dtbc_w[c*384 + kc*96 + kk];
        }
        __syncthreads();
        #pragma unroll 2
        for (int kk = 0; kk < 96; kk += 4) {
            float4 xq[4];
            #pragma unroll
            for (int q = 0; q < 4; q++)
                xq[q] = *(const float4*)&xs[(kk+q)*TTP + tx*4];
            #pragma unroll
            for (int j = 0; j < 3; j++) {
                int c = ty + 16*j;
                if (c < 38) {
                    const float* wrow = &ws[c*96];
                    FMA_GROUP16(j)
                }
            }
        }
    }
    __syncthreads();
    #pragma unroll
    for (int j = 0; j < 3; j++) {
        int c = ty + 16*j;
        if (c < 38) {
            float4 v; v.x = acc[0][j]; v.y = acc[1][j]; v.z = acc[2][j]; v.w = acc[3][j];
            *(float4*)&dbl[c*TTP + tx*4] = v;
        }
    }
    __syncthreads();

    for (int i = tid; i < DM*TT; i += 512) {
        int t = i % TT, d = i / TT;
        float s = 2.0f * dtb[d];
        #pragma unroll
        for (int r = 0; r < RT; r++) s = fmaf(dbl[r*TTP + t], dtw[d*RT + r], s);
        float dl = (s > 20.f) ? s : log1pf(__expf(s));
        g_dl[((size_t)b*DM + d)*L_ + l0 + t] = dl;
    }
    for (int i = tid; i < 2*NS*TT; i += 512) {
        int t = i % TT, q = i / TT;
        float v = dbl[(RT + q)*TTP + t];
        if (q < NS) g_Bs[((size_t)b*NS + q)*L_ + l0 + t] = v;
        else        g_Cs[((size_t)b*NS + (q-NS))*L_ + l0 + t] = v;
    }
}

/* ==== gate: z = silu(cat(xc,qp) @ gate_w^T + gate_b), N-half per block ==== */
__global__ void __launch_bounds__(512, 2)
gate_kernel(const float* __restrict__ gate_w, const float* __restrict__ gate_b)
{
    extern __shared__ float sm[];
    float* xs = sm;              // 96*TTP
    float* ws = xs + 96*TTP;     // 96*96
    int tid = threadIdx.x;
    int tok0 = blockIdx.x * TT;
    int c0 = blockIdx.y * 96;
    int b = tok0 / L_, l0 = tok0 % L_;
    int tx = tid & 31, ty = tid >> 5;

    float acc[4][6];
    #pragma unroll
    for (int m = 0; m < 4; m++)
        #pragma unroll
        for (int j = 0; j < 6; j++) acc[m][j] = 0.f;

    for (int kc = 0; kc < 4; kc++) {
        const float* src = (kc < 2) ? g_xc : g_qp;
        int k0 = (kc & 1) * 96;
        __syncthreads();
        for (int i = tid; i < 96*TT; i += 512) {
            int t = i % TT, k = i / TT;
            xs[k*TTP + t] = src[((size_t)b*DM + k0 + k)*L_ + l0 + t];
        }
        for (int i = tid; i < 96*96; i += 512) {
            int c = i / 96, kk = i % 96;
            ws[i] = gate_w[(size_t)(c0 + c)*384 + kc*96 + kk];
        }
        __syncthreads();
        #pragma unroll 2
        for (int kk = 0; kk < 96; kk += 4) {
            float4 xq[4];
            #pragma unroll
            for (int q = 0; q < 4; q++)
                xq[q] = *(const float4*)&xs[(kk+q)*TTP + tx*4];
            #pragma unroll
            for (int j = 0; j < 6; j++) {
                const float* wrow = &ws[(ty + 16*j)*96];
                FMA_GROUP16(j)
            }
        }
    }
    float* dstb = g_z + ((size_t)b*DM)*L_ + l0;
    #pragma unroll
    for (int j = 0; j < 6; j++) {
        int c = ty + 16*j;
        float bv = gate_b[c0 + c];
        float4 v;
        v.x = siluf(acc[0][j] + bv); v.y = siluf(acc[1][j] + bv);
        v.z = siluf(acc[2][j] + bv); v.w = siluf(acc[3][j] + bv);
        *(float4*)&dstb[(size_t)(c0 + c)*L_ + tx*4] = v;
    }
}

/* ============ chunked selective scan ============ */
__global__ void __launch_bounds__(256)
scan1(const float* __restrict__ A_log)
{
    __shared__ float dls[16*97], xcs[16*97], bs[16*97];
    int b = blockIdx.z, ch = blockIdx.y, dblk = blockIdx.x;
    int d0 = dblk*16;
    int tid = threadIdx.x;
    for (int i = tid; i < 16*G_; i += 256) {
        int r = i / G_, t = i % G_;
        dls[r*97+t] = g_dl[((size_t)b*DM + d0 + r)*L_ + ch*G_ + t];
        xcs[r*97+t] = g_xc[((size_t)b*DM + d0 + r)*L_ + ch*G_ + t];
        bs [r*97+t] = g_Bs[((size_t)b*NS + r)*L_ + ch*G_ + t];
    }
    __syncthreads();
    int n = tid & 15, dloc = tid >> 4;
    int d = d0 + dloc;
    float A = -__expf(A_log[d*NS + n]);
    float h = 0.f, S = 0.f;
    #pragma unroll 4
    for (int t = 0; t < G_; t++) {
        float dl = dls[dloc*97+t];
        float a = __expf(dl * A);
        S += dl;
        h = fmaf(a, h, dl * xcs[dloc*97+t] * bs[n*97+t]);
    }
    size_t o = (((size_t)(b*NCH + ch))*DM + d)*NS + n;
    g_P[o] = __expf(A * S); g_Hl[o] = h;
}

__global__ void __launch_bounds__(256)
scan2()
{
    int idx = blockIdx.x * blockDim.x + threadIdx.x;
    if (idx >= B_*DM*NS) return;
    int b = idx / (DM*NS);
    int dn = idx % (DM*NS);
    float h = 0.f;
    for (int ch = 0; ch < NCH; ch++) {
        size_t o = ((size_t)(b*NCH + ch))*(DM*NS) + dn;
        g_Hi[o] = h;
        h = fmaf(g_P[o], h, g_Hl[o]);
    }
}

__global__ void __launch_bounds__(256)
scan3(const float* __restrict__ A_log, const float* __restrict__ Dp)
{
    __shared__ float dls[16*97], xcs[16*97], bs[16*97], cs[16*97], zs[16*97], ys[16*97];
    int b = blockIdx.z, ch = blockIdx.y, dblk = blockIdx.x;
    int d0 = dblk*16;
    int tid = threadIdx.x;
    for (int i = tid; i < 16*G_; i += 256) {
        int r = i / G_, t = i % G_;
        size_t db = ((size_t)b*DM + d0 + r)*L_ + ch*G_ + t;
        size_t nb = ((size_t)b*NS + r)*L_ + ch*G_ + t;
        dls[r*97+t] = g_dl[db];
        xcs[r*97+t] = g_xc[db];
        zs [r*97+t] = g_z [db];
        bs [r*97+t] = g_Bs[nb];
        cs [r*97+t] = g_Cs[nb];
    }
    __syncthreads();
    int n = tid & 15, dloc = tid >> 4;
    int d = d0 + dloc;
    float A = -__expf(A_log[d*NS + n]);
    size_t o = (((size_t)(b*NCH + ch))*DM + d)*NS + n;
    float h = g_Hi[o];
    float Dd = Dp[d];
    for (int t = 0; t < G_; t++) {
        float dl = dls[dloc*97+t];
        float u  = xcs[dloc*97+t];
        float a = __expf(dl * A);
        h = fmaf(a, h, dl * u * bs[n*97+t]);
        float v = h * cs[n*97+t];
        v += __shfl_xor_sync(0xffffffffu, v, 1);
        v += __shfl_xor_sync(0xffffffffu, v, 2);
        v += __shfl_xor_sync(0xffffffffu, v, 4);
        v += __shfl_xor_sync(0xffffffffu, v, 8);
        if (n == 0)
            ys[dloc*97+t] = (v + u * Dd) * zs[dloc*97+t];
    }
    __syncthreads();
    for (int i = tid; i < 16*G_; i += 256) {
        int r = i / G_, t = i % G_;
        g_y[((size_t)b*DM + d0 + r)*L_ + ch*G_ + t] = ys[r*97+t];
    }
}

/* ==== out projection: N=96, K=192 staged in 2 chunks ==== */
__global__ void __launch_bounds__(512, 2)
gemm_out(const float* __restrict__ out_w, float* __restrict__ out)
{
    extern __shared__ float sm[];
    float* xs = sm;              // 96*TTP
    float* ws = xs + 96*TTP;     // 96*96 per chunk
    int tid = threadIdx.x;
    int tok0 = blockIdx.x * TT;
    int b = tok0 / L_, l0 = tok0 % L_;
    int tx = tid & 31, ty = tid >> 5;
    float acc[4][6];
    #pragma unroll
    for (int m = 0; m < 4; m++)
        #pragma unroll
        for (int j = 0; j < 6; j++) acc[m][j] = 0.f;

    for (int kc = 0; kc < 2; kc++) {
        __syncthreads();
        for (int i = tid; i < 96*TT; i += 512) {
            int t = i % TT, k = i / TT;
            xs[k*TTP + t] = g_y[((size_t)b*DM + kc*96 + k)*L_ + l0 + t];
        }
        for (int i = tid; i < 96*96; i += 512) {
            int c = i / 96, kk = i % 96;
            ws[i] = out_w[(size_t)c*DM + kc*96 + kk];
        }
        __syncthreads();
        #pragma unroll 2
        for (int kk = 0; kk < 96; kk += 4) {
            float4 xq[4];
            #pragma unroll
            for (int q = 0; q < 4; q++)
                xq[q] = *(const float4*)&xs[(kk+q)*TTP + tx*4];
            #pragma unroll
            for (int j = 0; j < 6; j++) {
                const float* wrow = &ws[(ty + 16*j)*96];
                FMA_GROUP16(j)
            }
        }
    }
    float* ob = out + ((size_t)b*CDIM)*L_ + l0;
    #pragma unroll
    for (int j = 0; j < 6; j++) {
        int c = ty + 16*j;
        float4 v; v.x = acc[0][j]; v.y = acc[1][j]; v.z = acc[2][j]; v.w = acc[3][j];
        *(float4*)&ob[(size_t)c*L_ + tx*4] = v;
    }
}

/* ============ host launcher ============ */
extern "C" void kernel_launch(void* const* d_in, const int* in_sizes, int n_in,
                              void* d_out, int out_size)
{
    const float* x         = (const float*)d_in[0];
    const float* Kin       = (const float*)d_in[1];
    const float* Qin       = (const float*)d_in[2];
    const float* in_proj_w = (const float*)d_in[3];
    const float* conv_w    = (const float*)d_in[4];
    const float* conv_b    = (const float*)d_in[5];
    const float* k_ln_g    = (const float*)d_in[6];
    const float* k_ln_b    = (const float*)d_in[7];
    const float* k_w       = (const float*)d_in[8];
    const float* k_b       = (const float*)d_in[9];
    const float* q_ln_g    = (const float*)d_in[10];
    const float* q_ln_b    = (const float*)d_in[11];
    const float* q_w       = (const float*)d_in[12];
    const float* q_b       = (const float*)d_in[13];
    const float* dtbc_w    = (const float*)d_in[14];
    const float* dt_w      = (const float*)d_in[15];
    const float* dt_b      = (const float*)d_in[16];
    const float* gate_w    = (const float*)d_in[17];
    const float* gate_b    = (const float*)d_in[18];
    const float* A_log     = (const float*)d_in[19];
    const float* Dp        = (const float*)d_in[20];
    const float* out_w     = (const float*)d_in[21];
    float* out = (float*)d_out;

    const int SMEM_A = (96*TTP + 96*96 + 256) * 4;            /* ~89 KB */
    const int SMEM_G = (96*TTP + 96*96) * 4;                  /* ~88 KB */
    const int SMEM_D = (96*TTP + 38*96 + 38*TTP + 192*6 + 192) * 4;  /* ~91 KB */
    const int SMEM_O = (96*TTP + 96*96) * 4;                  /* ~88 KB */

    cudaFuncSetAttribute(gemm3_k96,   cudaFuncAttributeMaxDynamicSharedMemorySize, SMEM_A);
    cudaFuncSetAttribute(gate_kernel, cudaFuncAttributeMaxDynamicSharedMemorySize, SMEM_G);
    cudaFuncSetAttribute(dtbc_kernel, cudaFuncAttributeMaxDynamicSharedMemorySize, SMEM_D);
    cudaFuncSetAttribute(gemm_out,    cudaFuncAttributeMaxDynamicSharedMemorySize, SMEM_O);

    /* 1. fused in_proj + K + Q, split over N halves (grid.z) */
    gemm3_k96<<<dim3(NTILE,3,2), 512, SMEM_A>>>(x, Kin, Qin, in_proj_w,
        k_w, k_b, k_ln_g, k_ln_b, q_w, q_b, q_ln_g, q_ln_b);
    /* 2. depthwise conv + silu */
    conv_silu<<<(B_*DM*L_)/256, 256>>>(conv_w, conv_b);
    /* 3. dtbc -> delta, B, C */
    dtbc_kernel<<<NTILE, 512, SMEM_D>>>(dtbc_w, dt_w, dt_b);
    /* 4. gate -> silu(z), split over N halves (grid.y) */
    gate_kernel<<<dim3(NTILE,2), 512, SMEM_G>>>(gate_w, gate_b);
    /* 5-7. chunked selective scan */
    scan1<<<dim3(DM/16, NCH, B_), 256>>>(A_log);
    scan2<<<(B_*DM*NS)/256, 256>>>();
    scan3<<<dim3(DM/16, NCH, B_), 256>>>(A_log, Dp);
    /* 8. output projection */
    gemm_out<<<NTILE, 512, SMEM_O>>>(out_w, out);
}

// round 11
// speedup vs baseline: 1.0587x; 1.0587x over previous
#include <cuda_runtime.h>

#define B_    4
#define CDIM  96
#define L_    9216
#define DM    192
#define NS    16
#define RT    6
#define BL    (B_*L_)
#define TT    128
#define NTILE (BL/TT)     /* 288 */
#define G_    96
#define NCH   (L_/G_)     /* 96 */
#define TTP   132         /* fp32 GEMM xs stride */
/* tf32 MMA kernel constants */
#define KCH   48          /* k-chunk */
#define TFP   136         /* tf32 xs stride (bank-clean for frag loads) */
#define WSTR  52          /* tf32 ws stride (bank-clean for frag loads) */

/* ---- scratch ---- */
__device__ float g_xin[(size_t)B_*DM*L_];
__device__ float g_xc [(size_t)B_*DM*L_];
__device__ float g_kp [(size_t)B_*DM*L_];
__device__ float g_qp [(size_t)B_*DM*L_];
__device__ float g_dl [(size_t)B_*DM*L_];
__device__ float g_z  [(size_t)B_*DM*L_];
__device__ float g_Bs [(size_t)B_*NS*L_];
__device__ float g_Cs [(size_t)B_*NS*L_];
__device__ float g_y  [(size_t)B_*DM*L_];
__device__ float g_P  [(size_t)B_*NCH*DM*NS];
__device__ float g_Hl [(size_t)B_*NCH*DM*NS];
__device__ float g_Hi [(size_t)B_*NCH*DM*NS];

__device__ __forceinline__ float siluf(float v) { return v / (1.0f + __expf(-v)); }

__device__ __forceinline__ unsigned tf32b(float v) {
    unsigned r; asm("cvt.rna.tf32.f32 %0, %1;" : "=r"(r) : "f"(v)); return r;
}

/* D += A(16x8,row) * B(8x8,col) in tf32 */
__device__ __forceinline__ void mma8(float* d, const unsigned* a, const unsigned* b) {
    asm volatile("mma.sync.aligned.m16n8k8.row.col.f32.tf32.tf32.f32 "
        "{%0,%1,%2,%3}, {%4,%5,%6,%7}, {%8,%9}, {%0,%1,%2,%3};"
        : "+f"(d[0]), "+f"(d[1]), "+f"(d[2]), "+f"(d[3])
        : "r"(a[0]), "r"(a[1]), "r"(a[2]), "r"(a[3]), "r"(b[0]), "r"(b[1]));
}

/* 16 FMAs: one float4 weight vector vs 4 float4 x vectors into acc[4][j] */
#define FMA_GROUP16(j)                                                   \
    {   float4 wq = *(const float4*)&wrow[kk];                           \
        acc[0][j] = fmaf(wq.x, xq[0].x, acc[0][j]);                      \
        acc[1][j] = fmaf(wq.x, xq[0].y, acc[1][j]);                      \
        acc[2][j] = fmaf(wq.x, xq[0].z, acc[2][j]);                      \
        acc[3][j] = fmaf(wq.x, xq[0].w, acc[3][j]);                      \
        acc[0][j] = fmaf(wq.y, xq[1].x, acc[0][j]);                      \
        acc[1][j] = fmaf(wq.y, xq[1].y, acc[1][j]);                      \
        acc[2][j] = fmaf(wq.y, xq[1].z, acc[2][j]);                      \
        acc[3][j] = fmaf(wq.y, xq[1].w, acc[3][j]);                      \
        acc[0][j] = fmaf(wq.z, xq[2].x, acc[0][j]);                      \
        acc[1][j] = fmaf(wq.z, xq[2].y, acc[1][j]);                      \
        acc[2][j] = fmaf(wq.z, xq[2].z, acc[2][j]);                      \
        acc[3][j] = fmaf(wq.z, xq[2].w, acc[3][j]);                      \
        acc[0][j] = fmaf(wq.w, xq[3].x, acc[0][j]);                      \
        acc[1][j] = fmaf(wq.w, xq[3].y, acc[1][j]);                      \
        acc[2][j] = fmaf(wq.w, xq[3].z, acc[2][j]);                      \
        acc[3][j] = fmaf(wq.w, xq[3].w, acc[3][j]); }

/* ============ fused 3x GEMM (in_proj / K / Q), fp32, R7 version ============ */
__global__ void __launch_bounds__(512)
gemm3_k96(const float* __restrict__ x, const float* __restrict__ Kin,
          const float* __restrict__ Qin, const float* __restrict__ in_w,
          const float* __restrict__ k_w, const float* __restrict__ k_b,
          const float* __restrict__ k_ln_g, const float* __restrict__ k_ln_b,
          const float* __restrict__ q_w, const float* __restrict__ q_b,
          const float* __restrict__ q_ln_g, const float* __restrict__ q_ln_b)
{
    extern __shared__ float sm[];
    float* xs = sm;                      // 96*TTP
    float* ws = sm + 96*TTP;             // 192*96
    float* mean_s = ws + 192*96;         // 128
    float* rstd_s = mean_s + 128;        // 128

    int sel = blockIdx.y;
    const float* src  = (sel==0) ? x    : (sel==1 ? Kin : Qin);
    const float* W    = (sel==0) ? in_w : (sel==1 ? k_w : q_w);
    const float* bias = (sel==0) ? 0    : (sel==1 ? k_b : q_b);
    const float* lng  = (sel==1) ? k_ln_g : q_ln_g;
    const float* lnb  = (sel==1) ? k_ln_b : q_ln_b;

    int tid = threadIdx.x;
    int tok0 = blockIdx.x * TT;
    int b = tok0 / L_, l0 = tok0 % L_;
    const float* srcb = src + ((size_t)b*CDIM)*L_ + l0;

    for (int i = tid; i < DM*CDIM; i += 512) ws[i] = W[i];
    for (int i = tid; i < CDIM*TT; i += 512) {
        int t = i % TT, k = i / TT;
        xs[k*TTP + t] = srcb[(size_t)k*L_ + t];
    }
    __syncthreads();

    if (sel != 0) {
        if (tid < TT) {
            float s = 0.f, ss = 0.f;
            for (int c = 0; c < CDIM; c++) { float v = xs[c*TTP + tid]; s += v; ss += v*v; }
            float m = s * (1.0f/CDIM);
            float var = ss * (1.0f/CDIM) - m*m;
            mean_s[tid] = m; rstd_s[tid] = rsqrtf(var + 1e-5f);
        }
        __syncthreads();
        for (int i = tid; i < CDIM*TT; i += 512) {
            int t = i % TT, c = i / TT;
            xs[c*TTP + t] = (xs[c*TTP + t] - mean_s[t]) * rstd_s[t] * lng[c] + lnb[c];
        }
        __syncthreads();
    }

    int tx = tid & 31, ty = tid >> 5;
    float acc[4][12];
    #pragma unroll
    for (int m = 0; m < 4; m++)
        #pragma unroll
        for (int j = 0; j < 12; j++) acc[m][j] = 0.f;

    #pragma unroll 2
    for (int kk = 0; kk < CDIM; kk += 4) {
        float4 xq[4];
        #pragma unroll
        for (int q = 0; q < 4; q++)
            xq[q] = *(const float4*)&xs[(kk+q)*TTP + tx*4];
        #pragma unroll
        for (int j = 0; j < 12; j++) {
            const float* wrow = &ws[(ty + 16*j)*CDIM];
            FMA_GROUP16(j)
        }
    }

    float* dst = (sel == 0) ? g_xin : ((sel == 1) ? g_kp : g_qp);
    float* dstb = dst + ((size_t)b*DM)*L_ + l0;
    #pragma unroll
    for (int j = 0; j < 12; j++) {
        int c = ty + 16*j;
        float bv = bias ? bias[c] : 0.f;
        float4 v;
        v.x = acc[0][j] + bv; v.y = acc[1][j] + bv;
        v.z = acc[2][j] + bv; v.w = acc[3][j] + bv;
        if (sel != 0) { v.x = siluf(v.x); v.y = siluf(v.y); v.z = siluf(v.z); v.w = siluf(v.w); }
        *(float4*)&dstb[(size_t)c*L_ + tx*4] = v;
    }
}

/* ============ depthwise causal conv (k=4) + silu ============ */
__global__ void __launch_bounds__(256)
conv_silu(const float* __restrict__ cw, const float* __restrict__ cb)
{
    int gid = blockIdx.x * blockDim.x + threadIdx.x;
    if (gid >= B_*DM*L_) return;
    int l  = gid % L_;
    int bd = gid / L_;
    int d  = bd % DM;
    const float* p = g_xin + (size_t)bd*L_ + l;
    float acc = cb[d] + cw[d*4+3] * p[0];
    if (l >= 1) acc = fmaf(cw[d*4+2], p[-1], acc);
    if (l >= 2) acc = fmaf(cw[d*4+1], p[-2], acc);
    if (l >= 3) acc = fmaf(cw[d*4+0], p[-3], acc);
    g_xc[gid] = siluf(acc);
}

/* ============ dtbc (fp32, R7 version) ============ */
__global__ void __launch_bounds__(512)
dtbc_kernel(const float* __restrict__ dtbc_w, const float* __restrict__ dt_w,
            const float* __restrict__ dt_b)
{
    extern __shared__ float sm[];
    float* xs   = sm;                    // 96*TTP
    float* ws   = xs + 96*TTP;           // 38*96
    float* dbl  = ws + 38*96;            // 38*TTP
    float* dtw  = dbl + 38*TTP;          // 192*6
    float* dtb  = dtw + 192*6;           // 192
    int tid = threadIdx.x;
    int tok0 = blockIdx.x * TT;
    int b = tok0 / L_, l0 = tok0 % L_;

    for (int i = tid; i < DM*RT; i += 512) dtw[i] = dt_w[i];
    for (int i = tid; i < DM;    i += 512) dtb[i] = dt_b[i];

    int tx = tid & 31, ty = tid >> 5;
    float acc[4][3];
    #pragma unroll
    for (int m = 0; m < 4; m++)
        #pragma unroll
        for (int j = 0; j < 3; j++) acc[m][j] = 0.f;

    for (int kc = 0; kc < 4; kc++) {
        const float* src = (kc < 2) ? g_xc : g_kp;
        int k0 = (kc & 1) * 96;
        __syncthreads();
        for (int i = tid; i < 96*TT; i += 512) {
            int t = i % TT, k = i / TT;
            xs[k*TTP + t] = src[((size_t)b*DM + k0 + k)*L_ + l0 + t];
        }
        for (int i = tid; i < 38*96; i += 512) {
            int c = i / 96, kk = i % 96;
            ws[i] = dtbc_w[c*384 + kc*96 + kk];
        }
        __syncthreads();
        #pragma unroll 2
        for (int kk = 0; kk < 96; kk += 4) {
            float4 xq[4];
            #pragma unroll
            for (int q = 0; q < 4; q++)
                xq[q] = *(const float4*)&xs[(kk+q)*TTP + tx*4];
            #pragma unroll
            for (int j = 0; j < 3; j++) {
                int c = ty + 16*j;
                if (c < 38) {
                    const float* wrow = &ws[c*96];
                    FMA_GROUP16(j)
                }
            }
        }
    }
    __syncthreads();
    #pragma unroll
    for (int j = 0; j < 3; j++) {
        int c = ty + 16*j;
        if (c < 38) {
            float4 v; v.x = acc[0][j]; v.y = acc[1][j]; v.z = acc[2][j]; v.w = acc[3][j];
            *(float4*)&dbl[c*TTP + tx*4] = v;
        }
    }
    __syncthreads();

    for (int i = tid; i < DM*TT; i += 512) {
        int t = i % TT, d = i / TT;
        float s = 2.0f * dtb[d];
        #pragma unroll
        for (int r = 0; r < RT; r++) s = fmaf(dbl[r*TTP + t], dtw[d*RT + r], s);
        float dl = (s > 20.f) ? s : log1pf(__expf(s));
        g_dl[((size_t)b*DM + d)*L_ + l0 + t] = dl;
    }
    for (int i = tid; i < 2*NS*TT; i += 512) {
        int t = i % TT, q = i / TT;
        float v = dbl[(RT + q)*TTP + t];
        if (q < NS) g_Bs[((size_t)b*NS + q)*L_ + l0 + t] = v;
        else        g_Cs[((size_t)b*NS + (q-NS))*L_ + l0 + t] = v;
    }
}

/* ==== gate (tf32 MMA, 3-term split): z = silu(cat(xc,qp) @ gate_w^T + b) ==== */
__global__ void __launch_bounds__(512)
gate_tf32(const float* __restrict__ gate_w, const float* __restrict__ gate_b)
{
    extern __shared__ float sm[];
    float* xh = sm;                  // KCH*TFP
    float* xl = xh + KCH*TFP;
    float* wh = xl + KCH*TFP;        // 192*WSTR
    float* wl = wh + 192*WSTR;
    int tid = threadIdx.x, lane = tid & 31, wid = tid >> 5;
    int tok0 = blockIdx.x * TT;
    int b = tok0 / L_, l0 = tok0 % L_;
    int wc = (wid & 3) * 48;         // channel base for this warp
    int wt = (wid >> 2) * 32;        // token base for this warp

    float acc[3][4][4];
    #pragma unroll
    for (int m = 0; m < 3; m++)
        #pragma unroll
        for (int n = 0; n < 4; n++)
            #pragma unroll
            for (int q = 0; q < 4; q++) acc[m][n][q] = 0.f;

    for (int kc = 0; kc < 8; kc++) {
        const float* src = (kc < 4) ? g_xc : g_qp;
        int ch0 = (kc & 3) * KCH;
        __syncthreads();
        for (int i = tid; i < KCH*TT; i += 512) {
            int t = i % TT, k = i / TT;
            float v = src[((size_t)b*DM + ch0 + k)*L_ + l0 + t];
            float hf = __uint_as_float(tf32b(v));
            xh[k*TFP + t] = hf;
            xl[k*TFP + t] = __uint_as_float(tf32b(v - hf));
        }
        for (int i = tid; i < DM*KCH; i += 512) {
            int c = i / KCH, k = i % KCH;
            float v = gate_w[(size_t)c*384 + kc*KCH + k];
            float hf = __uint_as_float(tf32b(v));
            wh[c*WSTR + k] = hf;
            wl[c*WSTR + k] = __uint_as_float(tf32b(v - hf));
        }
        __syncthreads();

        #pragma unroll
        for (int ks = 0; ks < KCH/8; ks++) {
            int kb = ks*8;
            unsigned bh[4][2], blo[4][2];
            #pragma unroll
            for (int n = 0; n < 4; n++) {
                int t = wt + n*8 + (lane>>2);
                int r0 = (kb + (lane&3))*TFP + t;
                int r1 = (kb + (lane&3) + 4)*TFP + t;
                bh [n][0] = __float_as_uint(xh[r0]);
                bh [n][1] = __float_as_uint(xh[r1]);
                blo[n][0] = __float_as_uint(xl[r0]);
                blo[n][1] = __float_as_uint(xl[r1]);
            }
            #pragma unroll
            for (int m = 0; m < 3; m++) {
                int c = wc + m*16 + (lane>>2);
                int a0 = c*WSTR + kb + (lane&3);
                int a1 = (c+8)*WSTR + kb + (lane&3);
                unsigned ah[4] = { __float_as_uint(wh[a0]), __float_as_uint(wh[a1]),
                                   __float_as_uint(wh[a0+4]), __float_as_uint(wh[a1+4]) };
                unsigned al[4] = { __float_as_uint(wl[a0]), __float_as_uint(wl[a1]),
                                   __float_as_uint(wl[a0+4]), __float_as_uint(wl[a1+4]) };
                #pragma unroll
                for (int n = 0; n < 4; n++) {
                    mma8(acc[m][n], ah, blo[n]);
                    mma8(acc[m][n], al, bh[n]);
                    mma8(acc[m][n], ah, bh[n]);
                }
            }
        }
    }

    float* dstb = g_z + ((size_t)b*DM)*L_ + l0;
    #pragma unroll
    for (int m = 0; m < 3; m++) {
        int c = wc + m*16 + (lane>>2);
        float bv0 = gate_b[c], bv1 = gate_b[c+8];
        #pragma unroll
        for (int n = 0; n < 4; n++) {
            int t = wt + n*8 + 2*(lane&3);
            float2 v0, v1;
            v0.x = siluf(acc[m][n][0] + bv0); v0.y = siluf(acc[m][n][1] + bv0);
            v1.x = siluf(acc[m][n][2] + bv1); v1.y = siluf(acc[m][n][3] + bv1);
            *(float2*)&dstb[(size_t)c*L_ + t] = v0;
            *(float2*)&dstb[(size_t)(c+8)*L_ + t] = v1;
        }
    }
}

/* ============ chunked selective scan ============ */
__global__ void __launch_bounds__(256)
scan1(const float* __restrict__ A_log)
{
    __shared__ float dls[16*97], xcs[16*97], bs[16*97];
    int b = blockIdx.z, ch = blockIdx.y, dblk = blockIdx.x;
    int d0 = dblk*16;
    int tid = threadIdx.x;
    for (int i = tid; i < 16*G_; i += 256) {
        int r = i / G_, t = i % G_;
        dls[r*97+t] = g_dl[((size_t)b*DM + d0 + r)*L_ + ch*G_ + t];
        xcs[r*97+t] = g_xc[((size_t)b*DM + d0 + r)*L_ + ch*G_ + t];
        bs [r*97+t] = g_Bs[((size_t)b*NS + r)*L_ + ch*G_ + t];
    }
    __syncthreads();
    int n = tid & 15, dloc = tid >> 4;
    int d = d0 + dloc;
    float A = -__expf(A_log[d*NS + n]);
    float h = 0.f, S = 0.f;
    #pragma unroll 4
    for (int t = 0; t < G_; t++) {
        float dl = dls[dloc*97+t];
        float a = __expf(dl * A);
        S += dl;
        h = fmaf(a, h, dl * xcs[dloc*97+t] * bs[n*97+t]);
    }
    size_t o = (((size_t)(b*NCH + ch))*DM + d)*NS + n;
    g_P[o] = __expf(A * S); g_Hl[o] = h;
}

__global__ void __launch_bounds__(256)
scan2()
{
    int idx = blockIdx.x * blockDim.x + threadIdx.x;
    if (idx >= B_*DM*NS) return;
    int b = idx / (DM*NS);
    int dn = idx % (DM*NS);
    float h = 0.f;
    for (int ch = 0; ch < NCH; ch++) {
        size_t o = ((size_t)(b*NCH + ch))*(DM*NS) + dn;
        g_Hi[o] = h;
        h = fmaf(g_P[o], h, g_Hl[o]);
    }
}

__global__ void __launch_bounds__(256)
scan3(const float* __restrict__ A_log, const float* __restrict__ Dp)
{
    __shared__ float dls[16*97], xcs[16*97], bs[16*97], cs[16*97], zs[16*97], ys[16*97];
    int b = blockIdx.z, ch = blockIdx.y, dblk = blockIdx.x;
    int d0 = dblk*16;
    int tid = threadIdx.x;
    for (int i = tid; i < 16*G_; i += 256) {
        int r = i / G_, t = i % G_;
        size_t db = ((size_t)b*DM + d0 + r)*L_ + ch*G_ + t;
        size_t nb = ((size_t)b*NS + r)*L_ + ch*G_ + t;
        dls[r*97+t] = g_dl[db];
        xcs[r*97+t] = g_xc[db];
        zs [r*97+t] = g_z [db];
        bs [r*97+t] = g_Bs[nb];
        cs [r*97+t] = g_Cs[nb];
    }
    __syncthreads();
    int n = tid & 15, dloc = tid >> 4;
    int d = d0 + dloc;
    float A = -__expf(A_log[d*NS + n]);
    size_t o = (((size_t)(b*NCH + ch))*DM + d)*NS + n;
    float h = g_Hi[o];
    float Dd = Dp[d];
    for (int t = 0; t < G_; t++) {
        float dl = dls[dloc*97+t];
        float u  = xcs[dloc*97+t];
        float a = __expf(dl * A);
        h = fmaf(a, h, dl * u * bs[n*97+t]);
        float v = h * cs[n*97+t];
        v += __shfl_xor_sync(0xffffffffu, v, 1);
        v += __shfl_xor_sync(0xffffffffu, v, 2);
        v += __shfl_xor_sync(0xffffffffu, v, 4);
        v += __shfl_xor_sync(0xffffffffu, v, 8);
        if (n == 0)
            ys[dloc*97+t] = (v + u * Dd) * zs[dloc*97+t];
    }
    __syncthreads();
    for (int i = tid; i < 16*G_; i += 256) {
        int r = i / G_, t = i % G_;
        g_y[((size_t)b*DM + d0 + r)*L_ + ch*G_ + t] = ys[r*97+t];
    }
}

/* ==== out projection (tf32 MMA, 3-term split): out = y @ out_w^T ==== */
__global__ void __launch_bounds__(512, 2)
gemm_out_tf32(const float* __restrict__ out_w, float* __restrict__ out)
{
    extern __shared__ float sm[];
    float* xh = sm;                  // KCH*TFP
    float* xl = xh + KCH*TFP;
    float* wh = xl + KCH*TFP;        // 96*WSTR
    float* wl = wh + 96*WSTR;
    int tid = threadIdx.x, lane = tid & 31, wid = tid >> 5;
    int tok0 = blockIdx.x * TT;
    int b = tok0 / L_, l0 = tok0 % L_;
    int wc = (wid & 1) * 48;
    int wt = (wid >> 1) * 16;

    float acc[3][2][4];
    #pragma unroll
    for (int m = 0; m < 3; m++)
        #pragma unroll
        for (int n = 0; n < 2; n++)
            #pragma unroll
            for (int q = 0; q < 4; q++) acc[m][n][q] = 0.f;

    for (int kc = 0; kc < 4; kc++) {
        __syncthreads();
        for (int i = tid; i < KCH*TT; i += 512) {
            int t = i % TT, k = i / TT;
            float v = g_y[((size_t)b*DM + kc*KCH + k)*L_ + l0 + t];
            float hf = __uint_as_float(tf32b(v));
            xh[k*TFP + t] = hf;
            xl[k*TFP + t] = __uint_as_float(tf32b(v - hf));
        }
        for (int i = tid; i < CDIM*KCH; i += 512) {
            int c = i / KCH, k = i % KCH;
            float v = out_w[(size_t)c*DM + kc*KCH + k];
            float hf = __uint_as_float(tf32b(v));
            wh[c*WSTR + k] = hf;
            wl[c*WSTR + k] = __uint_as_float(tf32b(v - hf));
        }
        __syncthreads();

        #pragma unroll
        for (int ks = 0; ks < KCH/8; ks++) {
            int kb = ks*8;
            unsigned bh[2][2], blo[2][2];
            #pragma unroll
            for (int n = 0; n < 2; n++) {
                int t = wt + n*8 + (lane>>2);
                int r0 = (kb + (lane&3))*TFP + t;
                int r1 = (kb + (lane&3) + 4)*TFP + t;
                bh [n][0] = __float_as_uint(xh[r0]);
                bh [n][1] = __float_as_uint(xh[r1]);
                blo[n][0] = __float_as_uint(xl[r0]);
                blo[n][1] = __float_as_uint(xl[r1]);
            }
            #pragma unroll
            for (int m = 0; m < 3; m++) {
                int c = wc + m*16 + (lane>>2);
                int a0 = c*WSTR + kb + (lane&3);
                int a1 = (c+8)*WSTR + kb + (lane&3);
                unsigned ah[4] = { __float_as_uint(wh[a0]), __float_as_uint(wh[a1]),
                                   __float_as_uint(wh[a0+4]), __float_as_uint(wh[a1+4]) };
                unsigned al[4] = { __float_as_uint(wl[a0]), __float_as_uint(wl[a1]),
                                   __float_as_uint(wl[a0+4]), __float_as_uint(wl[a1+4]) };
                #pragma unroll
                for (int n = 0; n < 2; n++) {
                    mma8(acc[m][n], ah, blo[n]);
                    mma8(acc[m][n], al, bh[n]);
                    mma8(acc[m][n], ah, bh[n]);
                }
            }
        }
    }

    float* ob = out + ((size_t)b*CDIM)*L_ + l0;
    #pragma unroll
    for (int m = 0; m < 3; m++) {
        int c = wc + m*16 + (lane>>2);
        #pragma unroll
        for (int n = 0; n < 2; n++) {
            int t = wt + n*8 + 2*(lane&3);
            float2 v0, v1;
            v0.x = acc[m][n][0]; v0.y = acc[m][n][1];
            v1.x = acc[m][n][2]; v1.y = acc[m][n][3];
            *(float2*)&ob[(size_t)c*L_ + t] = v0;
            *(float2*)&ob[(size_t)(c+8)*L_ + t] = v1;
        }
    }
}

/* ============ host launcher ============ */
extern "C" void kernel_launch(void* const* d_in, const int* in_sizes, int n_in,
                              void* d_out, int out_size)
{
    const float* x         = (const float*)d_in[0];
    const float* Kin       = (const float*)d_in[1];
    const float* Qin       = (const float*)d_in[2];
    const float* in_proj_w = (const float*)d_in[3];
    const float* conv_w    = (const float*)d_in[4];
    const float* conv_b    = (const float*)d_in[5];
    const float* k_ln_g    = (const float*)d_in[6];
    const float* k_ln_b    = (const float*)d_in[7];
    const float* k_w       = (const float*)d_in[8];
    const float* k_b       = (const float*)d_in[9];
    const float* q_ln_g    = (const float*)d_in[10];
    const float* q_ln_b    = (const float*)d_in[11];
    const float* q_w       = (const float*)d_in[12];
    const float* q_b       = (const float*)d_in[13];
    const float* dtbc_w    = (const float*)d_in[14];
    const float* dt_w      = (const float*)d_in[15];
    const float* dt_b      = (const float*)d_in[16];
    const float* gate_w    = (const float*)d_in[17];
    const float* gate_b    = (const float*)d_in[18];
    const float* A_log     = (const float*)d_in[19];
    const float* Dp        = (const float*)d_in[20];
    const float* out_w     = (const float*)d_in[21];
    float* out = (float*)d_out;

    const int SMEM_A  = (96*TTP + 192*96 + 256) * 4;                       /* ~123 KB */
    const int SMEM_D  = (96*TTP + 38*96 + 38*TTP + 192*6 + 192) * 4;       /* ~89 KB  */
    const int SMEM_GT = (2*KCH*TFP + 2*DM*WSTR) * 4;                       /* ~129 KB */
    const int SMEM_OT = (2*KCH*TFP + 2*CDIM*WSTR) * 4;                     /* ~71 KB  */

    cudaFuncSetAttribute(gemm3_k96,     cudaFuncAttributeMaxDynamicSharedMemorySize, SMEM_A);
    cudaFuncSetAttribute(dtbc_kernel,   cudaFuncAttributeMaxDynamicSharedMemorySize, SMEM_D);
    cudaFuncSetAttribute(gate_tf32,     cudaFuncAttributeMaxDynamicSharedMemorySize, SMEM_GT);
    cudaFuncSetAttribute(gemm_out_tf32, cudaFuncAttributeMaxDynamicSharedMemorySize, SMEM_OT);

    /* 1. fused in_proj + K + Q (fp32) */
    gemm3_k96<<<dim3(NTILE,3), 512, SMEM_A>>>(x, Kin, Qin, in_proj_w,
        k_w, k_b, k_ln_g, k_ln_b, q_w, q_b, q_ln_g, q_ln_b);
    /* 2. depthwise conv + silu */
    conv_silu<<<(B_*DM*L_)/256, 256>>>(conv_w, conv_b);
    /* 3. dtbc -> delta, B, C (fp32) */
    dtbc_kernel<<<NTILE, 512, SMEM_D>>>(dtbc_w, dt_w, dt_b);
    /* 4. gate -> silu(z) (tf32 tensor-core, 3-term split) */
    gate_tf32<<<NTILE, 512, SMEM_GT>>>(gate_w, gate_b);
    /* 5-7. chunked selective scan */
    scan1<<<dim3(DM/16, NCH, B_), 256>>>(A_log);
    scan2<<<(B_*DM*NS)/256, 256>>>();
    scan3<<<dim3(DM/16, NCH, B_), 256>>>(A_log, Dp);
    /* 8. output projection (tf32 tensor-core, 3-term split) */
    gemm_out_tf32<<<NTILE, 512, SMEM_OT>>>(out_w, out);
}

// round 12
// speedup vs baseline: 1.5228x; 1.4384x over previous
#include <cuda_runtime.h>

#define B_    4
#define CDIM  96
#define L_    9216
#define DM    192
#define NS    16
#define RT    6
#define BL    (B_*L_)
#define TT    128         /* dtbc / out tile */
#define NTILE (BL/TT)     /* 288 */
#define G_    96
#define NCH   (L_/G_)     /* 96 */
#define TTP   132         /* fp32 GEMM xs stride */

/* tf32 kernels */
#define GT_TT  64         /* gate/gemm3 token tile */
#define GT_XS  72         /* x stride for 64-token tiles */
#define OT_XS  136        /* x stride for 128-token tiles */
#define WS_G   52         /* w stride, 48-wide k-chunk */
#define WS_3   100        /* w stride, full K=96 */

/* ---- scratch ---- */
__device__ float g_xin[(size_t)B_*DM*L_];
__device__ float g_xc [(size_t)B_*DM*L_];
__device__ float g_kp [(size_t)B_*DM*L_];
__device__ float g_qp [(size_t)B_*DM*L_];
__device__ float g_dl [(size_t)B_*DM*L_];
__device__ float g_z  [(size_t)B_*DM*L_];
__device__ float g_Bs [(size_t)B_*NS*L_];
__device__ float g_Cs [(size_t)B_*NS*L_];
__device__ float g_y  [(size_t)B_*DM*L_];
__device__ float g_P  [(size_t)B_*NCH*DM*NS];
__device__ float g_Hl [(size_t)B_*NCH*DM*NS];
__device__ float g_Hi [(size_t)B_*NCH*DM*NS];

__device__ __forceinline__ float siluf(float v) { return v / (1.0f + __expf(-v)); }

__device__ __forceinline__ unsigned tf32b(float v) {
    unsigned r; asm("cvt.rna.tf32.f32 %0, %1;" : "=r"(r) : "f"(v)); return r;
}

__device__ __forceinline__ void mma8(float* d, const unsigned* a, const unsigned* b) {
    asm volatile("mma.sync.aligned.m16n8k8.row.col.f32.tf32.tf32.f32 "
        "{%0,%1,%2,%3}, {%4,%5,%6,%7}, {%8,%9}, {%0,%1,%2,%3};"
        : "+f"(d[0]), "+f"(d[1]), "+f"(d[2]), "+f"(d[3])
        : "r"(a[0]), "r"(a[1]), "r"(a[2]), "r"(a[3]), "r"(b[0]), "r"(b[1]));
}

/* B frag (2 regs hi + 2 lo) from raw smem, split in registers */
#define BFRAG(BH, BL_, Xs, STR, kb, t) {                                  \
    float v0_ = (Xs)[((kb)+(lane&3))*(STR) + (t)];                        \
    float v1_ = (Xs)[((kb)+(lane&3)+4)*(STR) + (t)];                      \
    BH[0] = tf32b(v0_); BL_[0] = tf32b(v0_ - __uint_as_float(BH[0]));     \
    BH[1] = tf32b(v1_); BL_[1] = tf32b(v1_ - __uint_as_float(BH[1])); }

/* A frag (4 regs hi + 4 lo) from raw smem */
#define AFRAG(AH, AL_, Ws, STR, c, kb) {                                  \
    int i0_ = (c)*(STR) + (kb) + (lane&3);                                \
    int i1_ = ((c)+8)*(STR) + (kb) + (lane&3);                            \
    float w0_ = (Ws)[i0_], w1_ = (Ws)[i1_];                               \
    float w2_ = (Ws)[i0_+4], w3_ = (Ws)[i1_+4];                           \
    AH[0]=tf32b(w0_); AL_[0]=tf32b(w0_-__uint_as_float(AH[0]));           \
    AH[1]=tf32b(w1_); AL_[1]=tf32b(w1_-__uint_as_float(AH[1]));           \
    AH[2]=tf32b(w2_); AL_[2]=tf32b(w2_-__uint_as_float(AH[2]));           \
    AH[3]=tf32b(w3_); AL_[3]=tf32b(w3_-__uint_as_float(AH[3])); }

/* ==== fused 3x GEMM (in_proj / K / Q) on tensor cores, LN fused ====
   TT=64 tokens, 512 thr = 4(ch-groups 48) x 4(tok-groups 16). K=96. */
__global__ void __launch_bounds__(512, 2)
gemm3_tf32(const float* __restrict__ x, const float* __restrict__ Kin,
           const float* __restrict__ Qin, const float* __restrict__ in_w,
           const float* __restrict__ k_w, const float* __restrict__ k_b,
           const float* __restrict__ k_ln_g, const float* __restrict__ k_ln_b,
           const float* __restrict__ q_w, const float* __restrict__ q_b,
           const float* __restrict__ q_ln_g, const float* __restrict__ q_ln_b)
{
    extern __shared__ float sm[];
    float* xs = sm;                      // 96*GT_XS
    float* ws = sm + 96*GT_XS;           // 192*WS_3
    float* mean_s = ws + 192*WS_3;       // 64
    float* rstd_s = mean_s + 64;         // 64

    int sel = blockIdx.y;
    const float* src  = (sel==0) ? x    : (sel==1 ? Kin : Qin);
    const float* W    = (sel==0) ? in_w : (sel==1 ? k_w : q_w);
    const float* bias = (sel==0) ? 0    : (sel==1 ? k_b : q_b);
    const float* lng  = (sel==1) ? k_ln_g : q_ln_g;
    const float* lnb  = (sel==1) ? k_ln_b : q_ln_b;

    int tid = threadIdx.x, lane = tid & 31, wid = tid >> 5;
    int tok0 = blockIdx.x * GT_TT;
    int b = tok0 / L_, l0 = tok0 % L_;
    const float* srcb = src + ((size_t)b*CDIM)*L_ + l0;

    for (int i = tid; i < DM*CDIM; i += 512) ws[(i/CDIM)*WS_3 + (i%CDIM)] = W[i];
    for (int i = tid; i < CDIM*GT_TT; i += 512) {
        int t = i % GT_TT, k = i / GT_TT;
        xs[k*GT_XS + t] = srcb[(size_t)k*L_ + t];
    }
    __syncthreads();

    if (sel != 0) {
        if (tid < GT_TT) {
            float s = 0.f, ss = 0.f;
            for (int c = 0; c < CDIM; c++) { float v = xs[c*GT_XS + tid]; s += v; ss += v*v; }
            float m = s * (1.0f/CDIM);
            float var = ss * (1.0f/CDIM) - m*m;
            mean_s[tid] = m; rstd_s[tid] = rsqrtf(var + 1e-5f);
        }
        __syncthreads();
        for (int i = tid; i < CDIM*GT_TT; i += 512) {
            int t = i % GT_TT, c = i / GT_TT;
            xs[c*GT_XS + t] = (xs[c*GT_XS + t] - mean_s[t]) * rstd_s[t] * lng[c] + lnb[c];
        }
        __syncthreads();
    }

    int wc = (wid & 3) * 48;         // channel group
    int wt = (wid >> 2) * 16;        // token group

    float acc[3][2][4];
    #pragma unroll
    for (int m = 0; m < 3; m++)
        #pragma unroll
        for (int n = 0; n < 2; n++)
            #pragma unroll
            for (int q = 0; q < 4; q++) acc[m][n][q] = 0.f;

    #pragma unroll
    for (int ks = 0; ks < CDIM/8; ks++) {
        int kb = ks*8;
        unsigned bh[2][2], bl[2][2];
        #pragma unroll
        for (int n = 0; n < 2; n++) {
            int t = wt + n*8 + (lane>>2);
            BFRAG(bh[n], bl[n], xs, GT_XS, kb, t)
        }
        #pragma unroll
        for (int m = 0; m < 3; m++) {
            unsigned ah[4], al[4];
            AFRAG(ah, al, ws, WS_3, wc + m*16 + (lane>>2), kb)
            #pragma unroll
            for (int n = 0; n < 2; n++) {
                mma8(acc[m][n], ah, bl[n]);
                mma8(acc[m][n], al, bh[n]);
                mma8(acc[m][n], ah, bh[n]);
            }
        }
    }

    float* dst = (sel == 0) ? g_xin : ((sel == 1) ? g_kp : g_qp);
    float* dstb = dst + ((size_t)b*DM)*L_ + l0;
    #pragma unroll
    for (int m = 0; m < 3; m++) {
        int c = wc + m*16 + (lane>>2);
        float bv0 = bias ? bias[c] : 0.f;
        float bv1 = bias ? bias[c+8] : 0.f;
        #pragma unroll
        for (int n = 0; n < 2; n++) {
            int t = wt + n*8 + 2*(lane&3);
            float2 v0, v1;
            v0.x = acc[m][n][0] + bv0; v0.y = acc[m][n][1] + bv0;
            v1.x = acc[m][n][2] + bv1; v1.y = acc[m][n][3] + bv1;
            if (sel != 0) { v0.x = siluf(v0.x); v0.y = siluf(v0.y);
                            v1.x = siluf(v1.x); v1.y = siluf(v1.y); }
            *(float2*)&dstb[(size_t)c*L_ + t] = v0;
            *(float2*)&dstb[(size_t)(c+8)*L_ + t] = v1;
        }
    }
}

/* ============ depthwise causal conv (k=4) + silu ============ */
__global__ void __launch_bounds__(256)
conv_silu(const float* __restrict__ cw, const float* __restrict__ cb)
{
    int gid = blockIdx.x * blockDim.x + threadIdx.x;
    if (gid >= B_*DM*L_) return;
    int l  = gid % L_;
    int bd = gid / L_;
    int d  = bd % DM;
    const float* p = g_xin + (size_t)bd*L_ + l;
    float acc = cb[d] + cw[d*4+3] * p[0];
    if (l >= 1) acc = fmaf(cw[d*4+2], p[-1], acc);
    if (l >= 2) acc = fmaf(cw[d*4+1], p[-2], acc);
    if (l >= 3) acc = fmaf(cw[d*4+0], p[-3], acc);
    g_xc[gid] = siluf(acc);
}

/* ============ dtbc (fp32, proven R7 version) ============ */
#define FMA_GROUP16(j)                                                   \
    {   float4 wq = *(const float4*)&wrow[kk];                           \
        acc[0][j] = fmaf(wq.x, xq[0].x, acc[0][j]);                      \
        acc[1][j] = fmaf(wq.x, xq[0].y, acc[1][j]);                      \
        acc[2][j] = fmaf(wq.x, xq[0].z, acc[2][j]);                      \
        acc[3][j] = fmaf(wq.x, xq[0].w, acc[3][j]);                      \
        acc[0][j] = fmaf(wq.y, xq[1].x, acc[0][j]);                      \
        acc[1][j] = fmaf(wq.y, xq[1].y, acc[1][j]);                      \
        acc[2][j] = fmaf(wq.y, xq[1].z, acc[2][j]);                      \
        acc[3][j] = fmaf(wq.y, xq[1].w, acc[3][j]);                      \
        acc[0][j] = fmaf(wq.z, xq[2].x, acc[0][j]);                      \
        acc[1][j] = fmaf(wq.z, xq[2].y, acc[1][j]);                      \
        acc[2][j] = fmaf(wq.z, xq[2].z, acc[2][j]);                      \
        acc[3][j] = fmaf(wq.z, xq[2].w, acc[3][j]);                      \
        acc[0][j] = fmaf(wq.w, xq[3].x, acc[0][j]);                      \
        acc[1][j] = fmaf(wq.w, xq[3].y, acc[1][j]);                      \
        acc[2][j] = fmaf(wq.w, xq[3].z, acc[2][j]);                      \
        acc[3][j] = fmaf(wq.w, xq[3].w, acc[3][j]); }

__global__ void __launch_bounds__(512)
dtbc_kernel(const float* __restrict__ dtbc_w, const float* __restrict__ dt_w,
            const float* __restrict__ dt_b)
{
    extern __shared__ float sm[];
    float* xs   = sm;                    // 96*TTP
    float* ws   = xs + 96*TTP;           // 38*96
    float* dbl  = ws + 38*96;            // 38*TTP
    float* dtw  = dbl + 38*TTP;          // 192*6
    float* dtb  = dtw + 192*6;           // 192
    int tid = threadIdx.x;
    int tok0 = blockIdx.x * TT;
    int b = tok0 / L_, l0 = tok0 % L_;

    for (int i = tid; i < DM*RT; i += 512) dtw[i] = dt_w[i];
    for (int i = tid; i < DM;    i += 512) dtb[i] = dt_b[i];

    int tx = tid & 31, ty = tid >> 5;
    float acc[4][3];
    #pragma unroll
    for (int m = 0; m < 4; m++)
        #pragma unroll
        for (int j = 0; j < 3; j++) acc[m][j] = 0.f;

    for (int kc = 0; kc < 4; kc++) {
        const float* src = (kc < 2) ? g_xc : g_kp;
        int k0 = (kc & 1) * 96;
        __syncthreads();
        for (int i = tid; i < 96*TT; i += 512) {
            int t = i % TT, k = i / TT;
            xs[k*TTP + t] = src[((size_t)b*DM + k0 + k)*L_ + l0 + t];
        }
        for (int i = tid; i < 38*96; i += 512) {
            int c = i / 96, kk = i % 96;
            ws[i] = dtbc_w[c*384 + kc*96 + kk];
        }
        __syncthreads();
        #pragma unroll 2
        for (int kk = 0; kk < 96; kk += 4) {
            float4 xq[4];
            #pragma unroll
            for (int q = 0; q < 4; q++)
                xq[q] = *(const float4*)&xs[(kk+q)*TTP + tx*4];
            #pragma unroll
            for (int j = 0; j < 3; j++) {
                int c = ty + 16*j;
                if (c < 38) {
                    const float* wrow = &ws[c*96];
                    FMA_GROUP16(j)
                }
            }
        }
    }
    __syncthreads();
    #pragma unroll
    for (int j = 0; j < 3; j++) {
        int c = ty + 16*j;
        if (c < 38) {
            float4 v; v.x = acc[0][j]; v.y = acc[1][j]; v.z = acc[2][j]; v.w = acc[3][j];
            *(float4*)&dbl[c*TTP + tx*4] = v;
        }
    }
    __syncthreads();

    for (int i = tid; i < DM*TT; i += 512) {
        int t = i % TT, d = i / TT;
        float s = 2.0f * dtb[d];
        #pragma unroll
        for (int r = 0; r < RT; r++) s = fmaf(dbl[r*TTP + t], dtw[d*RT + r], s);
        float dl = (s > 20.f) ? s : log1pf(__expf(s));
        g_dl[((size_t)b*DM + d)*L_ + l0 + t] = dl;
    }
    for (int i = tid; i < 2*NS*TT; i += 512) {
        int t = i % TT, q = i / TT;
        float v = dbl[(RT + q)*TTP + t];
        if (q < NS) g_Bs[((size_t)b*NS + q)*L_ + l0 + t] = v;
        else        g_Cs[((size_t)b*NS + (q-NS))*L_ + l0 + t] = v;
    }
}

/* ==== gate on tensor cores: z = silu(cat(xc,qp) @ gate_w^T + b) ====
   TT=64 tokens, K=384 in 8 chunks of 48. */
__global__ void __launch_bounds__(512, 2)
gate_tf32(const float* __restrict__ gate_w, const float* __restrict__ gate_b)
{
    extern __shared__ float sm[];
    float* xs = sm;                  // 48*GT_XS
    float* ws = xs + 48*GT_XS;       // 192*WS_G
    int tid = threadIdx.x, lane = tid & 31, wid = tid >> 5;
    int tok0 = blockIdx.x * GT_TT;
    int b = tok0 / L_, l0 = tok0 % L_;
    int wc = (wid & 3) * 48;
    int wt = (wid >> 2) * 16;

    float acc[3][2][4];
    #pragma unroll
    for (int m = 0; m < 3; m++)
        #pragma unroll
        for (int n = 0; n < 2; n++)
            #pragma unroll
            for (int q = 0; q < 4; q++) acc[m][n][q] = 0.f;

    for (int kc = 0; kc < 8; kc++) {
        const float* src = (kc < 4) ? g_xc : g_qp;
        int ch0 = (kc & 3) * 48;
        __syncthreads();
        for (int i = tid; i < 48*GT_TT; i += 512) {
            int t = i % GT_TT, k = i / GT_TT;
            xs[k*GT_XS + t] = src[((size_t)b*DM + ch0 + k)*L_ + l0 + t];
        }
        for (int i = tid; i < DM*48; i += 512) {
            int c = i / 48, k = i % 48;
            ws[c*WS_G + k] = gate_w[(size_t)c*384 + kc*48 + k];
        }
        __syncthreads();

        #pragma unroll
        for (int ks = 0; ks < 6; ks++) {
            int kb = ks*8;
            unsigned bh[2][2], bl[2][2];
            #pragma unroll
            for (int n = 0; n < 2; n++) {
                int t = wt + n*8 + (lane>>2);
                BFRAG(bh[n], bl[n], xs, GT_XS, kb, t)
            }
            #pragma unroll
            for (int m = 0; m < 3; m++) {
                unsigned ah[4], al[4];
                AFRAG(ah, al, ws, WS_G, wc + m*16 + (lane>>2), kb)
                #pragma unroll
                for (int n = 0; n < 2; n++) {
                    mma8(acc[m][n], ah, bl[n]);
                    mma8(acc[m][n], al, bh[n]);
                    mma8(acc[m][n], ah, bh[n]);
                }
            }
        }
    }

    float* dstb = g_z + ((size_t)b*DM)*L_ + l0;
    #pragma unroll
    for (int m = 0; m < 3; m++) {
        int c = wc + m*16 + (lane>>2);
        float bv0 = gate_b[c], bv1 = gate_b[c+8];
        #pragma unroll
        for (int n = 0; n < 2; n++) {
            int t = wt + n*8 + 2*(lane&3);
            float2 v0, v1;
            v0.x = siluf(acc[m][n][0] + bv0); v0.y = siluf(acc[m][n][1] + bv0);
            v1.x = siluf(acc[m][n][2] + bv1); v1.y = siluf(acc[m][n][3] + bv1);
            *(float2*)&dstb[(size_t)c*L_ + t] = v0;
            *(float2*)&dstb[(size_t)(c+8)*L_ + t] = v1;
        }
    }
}

/* ============ chunked selective scan (unchanged) ============ */
__global__ void __launch_bounds__(256)
scan1(const float* __restrict__ A_log)
{
    __shared__ float dls[16*97], xcs[16*97], bs[16*97];
    int b = blockIdx.z, ch = blockIdx.y, dblk = blockIdx.x;
    int d0 = dblk*16;
    int tid = threadIdx.x;
    for (int i = tid; i < 16*G_; i += 256) {
        int r = i / G_, t = i % G_;
        dls[r*97+t] = g_dl[((size_t)b*DM + d0 + r)*L_ + ch*G_ + t];
        xcs[r*97+t] = g_xc[((size_t)b*DM + d0 + r)*L_ + ch*G_ + t];
        bs [r*97+t] = g_Bs[((size_t)b*NS + r)*L_ + ch*G_ + t];
    }
    __syncthreads();
    int n = tid & 15, dloc = tid >> 4;
    int d = d0 + dloc;
    float A = -__expf(A_log[d*NS + n]);
    float h = 0.f, S = 0.f;
    #pragma unroll 4
    for (int t = 0; t < G_; t++) {
        float dl = dls[dloc*97+t];
        float a = __expf(dl * A);
        S += dl;
        h = fmaf(a, h, dl * xcs[dloc*97+t] * bs[n*97+t]);
    }
    size_t o = (((size_t)(b*NCH + ch))*DM + d)*NS + n;
    g_P[o] = __expf(A * S); g_Hl[o] = h;
}

__global__ void __launch_bounds__(256)
scan2()
{
    int idx = blockIdx.x * blockDim.x + threadIdx.x;
    if (idx >= B_*DM*NS) return;
    int b = idx / (DM*NS);
    int dn = idx % (DM*NS);
    float h = 0.f;
    for (int ch = 0; ch < NCH; ch++) {
        size_t o = ((size_t)(b*NCH + ch))*(DM*NS) + dn;
        g_Hi[o] = h;
        h = fmaf(g_P[o], h, g_Hl[o]);
    }
}

__global__ void __launch_bounds__(256)
scan3(const float* __restrict__ A_log, const float* __restrict__ Dp)
{
    __shared__ float dls[16*97], xcs[16*97], bs[16*97], cs[16*97], zs[16*97], ys[16*97];
    int b = blockIdx.z, ch = blockIdx.y, dblk = blockIdx.x;
    int d0 = dblk*16;
    int tid = threadIdx.x;
    for (int i = tid; i < 16*G_; i += 256) {
        int r = i / G_, t = i % G_;
        size_t db = ((size_t)b*DM + d0 + r)*L_ + ch*G_ + t;
        size_t nb = ((size_t)b*NS + r)*L_ + ch*G_ + t;
        dls[r*97+t] = g_dl[db];
        xcs[r*97+t] = g_xc[db];
        zs [r*97+t] = g_z [db];
        bs [r*97+t] = g_Bs[nb];
        cs [r*97+t] = g_Cs[nb];
    }
    __syncthreads();
    int n = tid & 15, dloc = tid >> 4;
    int d = d0 + dloc;
    float A = -__expf(A_log[d*NS + n]);
    size_t o = (((size_t)(b*NCH + ch))*DM + d)*NS + n;
    float h = g_Hi[o];
    float Dd = Dp[d];
    for (int t = 0; t < G_; t++) {
        float dl = dls[dloc*97+t];
        float u  = xcs[dloc*97+t];
        float a = __expf(dl * A);
        h = fmaf(a, h, dl * u * bs[n*97+t]);
        float v = h * cs[n*97+t];
        v += __shfl_xor_sync(0xffffffffu, v, 1);
        v += __shfl_xor_sync(0xffffffffu, v, 2);
        v += __shfl_xor_sync(0xffffffffu, v, 4);
        v += __shfl_xor_sync(0xffffffffu, v, 8);
        if (n == 0)
            ys[dloc*97+t] = (v + u * Dd) * zs[dloc*97+t];
    }
    __syncthreads();
    for (int i = tid; i < 16*G_; i += 256) {
        int r = i / G_, t = i % G_;
        g_y[((size_t)b*DM + d0 + r)*L_ + ch*G_ + t] = ys[r*97+t];
    }
}

/* ==== out projection on tensor cores: out = y @ out_w^T ====
   TT=128 tokens, N=96, K=192 in 4 chunks of 48. 16 warps = 2 x 8. */
__global__ void __launch_bounds__(512, 2)
gemm_out_tf32(const float* __restrict__ out_w, float* __restrict__ out)
{
    extern __shared__ float sm[];
    float* xs = sm;                  // 48*OT_XS
    float* ws = xs + 48*OT_XS;       // 96*WS_G
    int tid = threadIdx.x, lane = tid & 31, wid = tid >> 5;
    int tok0 = blockIdx.x * TT;
    int b = tok0 / L_, l0 = tok0 % L_;
    int wc = (wid & 1) * 48;
    int wt = (wid >> 1) * 16;

    float acc[3][2][4];
    #pragma unroll
    for (int m = 0; m < 3; m++)
        #pragma unroll
        for (int n = 0; n < 2; n++)
            #pragma unroll
            for (int q = 0; q < 4; q++) acc[m][n][q] = 0.f;

    for (int kc = 0; kc < 4; kc++) {
        __syncthreads();
        for (int i = tid; i < 48*TT; i += 512) {
            int t = i % TT, k = i / TT;
            xs[k*OT_XS + t] = g_y[((size_t)b*DM + kc*48 + k)*L_ + l0 + t];
        }
        for (int i = tid; i < CDIM*48; i += 512) {
            int c = i / 48, k = i % 48;
            ws[c*WS_G + k] = out_w[(size_t)c*DM + kc*48 + k];
        }
        __syncthreads();

        #pragma unroll
        for (int ks = 0; ks < 6; ks++) {
            int kb = ks*8;
            unsigned bh[2][2], bl[2][2];
            #pragma unroll
            for (int n = 0; n < 2; n++) {
                int t = wt + n*8 + (lane>>2);
                BFRAG(bh[n], bl[n], xs, OT_XS, kb, t)
            }
            #pragma unroll
            for (int m = 0; m < 3; m++) {
                unsigned ah[4], al[4];
                AFRAG(ah, al, ws, WS_G, wc + m*16 + (lane>>2), kb)
                #pragma unroll
                for (int n = 0; n < 2; n++) {
                    mma8(acc[m][n], ah, bl[n]);
                    mma8(acc[m][n], al, bh[n]);
                    mma8(acc[m][n], ah, bh[n]);
                }
            }
        }
    }

    float* ob = out + ((size_t)b*CDIM)*L_ + l0;
    #pragma unroll
    for (int m = 0; m < 3; m++) {
        int c = wc + m*16 + (lane>>2);
        #pragma unroll
        for (int n = 0; n < 2; n++) {
            int t = wt + n*8 + 2*(lane&3);
            float2 v0, v1;
            v0.x = acc[m][n][0]; v0.y = acc[m][n][1];
            v1.x = acc[m][n][2]; v1.y = acc[m][n][3];
            *(float2*)&ob[(size_t)c*L_ + t] = v0;
            *(float2*)&ob[(size_t)(c+8)*L_ + t] = v1;
        }
    }
}

/* ============ host launcher ============ */
extern "C" void kernel_launch(void* const* d_in, const int* in_sizes, int n_in,
                              void* d_out, int out_size)
{
    const float* x         = (const float*)d_in[0];
    const float* Kin       = (const float*)d_in[1];
    const float* Qin       = (const float*)d_in[2];
    const float* in_proj_w = (const float*)d_in[3];
    const float* conv_w    = (const float*)d_in[4];
    const float* conv_b    = (const float*)d_in[5];
    const float* k_ln_g    = (const float*)d_in[6];
    const float* k_ln_b    = (const float*)d_in[7];
    const float* k_w       = (const float*)d_in[8];
    const float* k_b       = (const float*)d_in[9];
    const float* q_ln_g    = (const float*)d_in[10];
    const float* q_ln_b    = (const float*)d_in[11];
    const float* q_w       = (const float*)d_in[12];
    const float* q_b       = (const float*)d_in[13];
    const float* dtbc_w    = (const float*)d_in[14];
    const float* dt_w      = (const float*)d_in[15];
    const float* dt_b      = (const float*)d_in[16];
    const float* gate_w    = (const float*)d_in[17];
    const float* gate_b    = (const float*)d_in[18];
    const float* A_log     = (const float*)d_in[19];
    const float* Dp        = (const float*)d_in[20];
    const float* out_w     = (const float*)d_in[21];
    float* out = (float*)d_out;

    const int SMEM_G3 = (96*GT_XS + 192*WS_3 + 128) * 4;                  /* ~102 KB */
    const int SMEM_D  = (96*TTP + 38*96 + 38*TTP + 192*6 + 192) * 4;      /* ~89 KB  */
    const int SMEM_GT = (48*GT_XS + 192*WS_G) * 4;                        /* ~53 KB  */
    const int SMEM_OT = (48*OT_XS + 96*WS_G) * 4;                         /* ~45 KB  */

    cudaFuncSetAttribute(gemm3_tf32,    cudaFuncAttributeMaxDynamicSharedMemorySize, SMEM_G3);
    cudaFuncSetAttribute(dtbc_kernel,   cudaFuncAttributeMaxDynamicSharedMemorySize, SMEM_D);
    cudaFuncSetAttribute(gate_tf32,     cudaFuncAttributeMaxDynamicSharedMemorySize, SMEM_GT);
    cudaFuncSetAttribute(gemm_out_tf32, cudaFuncAttributeMaxDynamicSharedMemorySize, SMEM_OT);

    /* 1. fused in_proj + K + Q (tensor cores, LN fused) */
    gemm3_tf32<<<dim3(BL/GT_TT,3), 512, SMEM_G3>>>(x, Kin, Qin, in_proj_w,
        k_w, k_b, k_ln_g, k_ln_b, q_w, q_b, q_ln_g, q_ln_b);
    /* 2. depthwise conv + silu */
    conv_silu<<<(B_*DM*L_)/256, 256>>>(conv_w, conv_b);
    /* 3. dtbc -> delta, B, C (fp32) */
    dtbc_kernel<<<NTILE, 512, SMEM_D>>>(dtbc_w, dt_w, dt_b);
    /* 4. gate -> silu(z) (tensor cores) */
    gate_tf32<<<BL/GT_TT, 512, SMEM_GT>>>(gate_w, gate_b);
    /* 5-7. chunked selective scan */
    scan1<<<dim3(DM/16, NCH, B_), 256>>>(A_log);
    scan2<<<(B_*DM*NS)/256, 256>>>();
    scan3<<<dim3(DM/16, NCH, B_), 256>>>(A_log, Dp);
    /* 8. output projection (tensor cores) */
    gemm_out_tf32<<<NTILE, 512, SMEM_OT>>>(out_w, out);
}

// round 13
// speedup vs baseline: 1.6200x; 1.0638x over previous
#include <cuda_runtime.h>

#define B_    4
#define CDIM  96
#define L_    9216
#define DM    192
#define NS    16
#define RT    6
#define BL    (B_*L_)
#define TT    128         /* dtbc / out tile */
#define NTILE (BL/TT)     /* 288 */
#define G_    96
#define NCH   (L_/G_)     /* 96 */
#define TTP   132         /* fp32 GEMM xs stride */

/* tf32 kernels */
#define GT_TT  64         /* gate/gemm3 token tile */
#define GT_XS  72         /* x stride for 64-token tiles */
#define OT_XS  136        /* x stride for 128-token tiles */
#define WS_G   52         /* w stride, 48-wide k-chunk */

/* ---- scratch ---- */
__device__ float g_xin[(size_t)B_*DM*L_];
__device__ float g_xc [(size_t)B_*DM*L_];
__device__ float g_kp [(size_t)B_*DM*L_];
__device__ float g_qp [(size_t)B_*DM*L_];
__device__ float g_dl [(size_t)B_*DM*L_];
__device__ float g_z  [(size_t)B_*DM*L_];
__device__ float g_Bs [(size_t)B_*NS*L_];
__device__ float g_Cs [(size_t)B_*NS*L_];
__device__ float g_y  [(size_t)B_*DM*L_];
__device__ float g_P  [(size_t)B_*NCH*DM*NS];
__device__ float g_Hl [(size_t)B_*NCH*DM*NS];
__device__ float g_Hi [(size_t)B_*NCH*DM*NS];

__device__ __forceinline__ float siluf(float v) { return v / (1.0f + __expf(-v)); }

__device__ __forceinline__ unsigned tf32b(float v) {
    unsigned r; asm("cvt.rna.tf32.f32 %0, %1;" : "=r"(r) : "f"(v)); return r;
}

__device__ __forceinline__ void mma8(float* d, const unsigned* a, const unsigned* b) {
    asm volatile("mma.sync.aligned.m16n8k8.row.col.f32.tf32.tf32.f32 "
        "{%0,%1,%2,%3}, {%4,%5,%6,%7}, {%8,%9}, {%0,%1,%2,%3};"
        : "+f"(d[0]), "+f"(d[1]), "+f"(d[2]), "+f"(d[3])
        : "r"(a[0]), "r"(a[1]), "r"(a[2]), "r"(a[3]), "r"(b[0]), "r"(b[1]));
}

/* B frag: 2 raw LDS -> register split into hi/lo */
#define BFRAG(BH, BL_, Xs, STR, kb, t) {                                  \
    float v0_ = (Xs)[((kb)+(lane&3))*(STR) + (t)];                        \
    float v1_ = (Xs)[((kb)+(lane&3)+4)*(STR) + (t)];                      \
    BH[0] = tf32b(v0_); BL_[0] = tf32b(v0_ - __uint_as_float(BH[0]));     \
    BH[1] = tf32b(v1_); BL_[1] = tf32b(v1_ - __uint_as_float(BH[1])); }

/* A frag: pure LDS from precomputed hi/lo smem planes */
#define AFRAG_S(AH, AL_, Wh, Wl, STR, c, kb) {                            \
    int i0_ = (c)*(STR) + (kb) + (lane&3);                                \
    int i1_ = ((c)+8)*(STR) + (kb) + (lane&3);                            \
    AH[0] = __float_as_uint((Wh)[i0_]);                                   \
    AH[1] = __float_as_uint((Wh)[i1_]);                                   \
    AH[2] = __float_as_uint((Wh)[i0_+4]);                                 \
    AH[3] = __float_as_uint((Wh)[i1_+4]);                                 \
    AL_[0] = __float_as_uint((Wl)[i0_]);                                  \
    AL_[1] = __float_as_uint((Wl)[i1_]);                                  \
    AL_[2] = __float_as_uint((Wl)[i0_+4]);                                \
    AL_[3] = __float_as_uint((Wl)[i1_+4]); }

/* stage a weight chunk (NC rows x 48 k) into hi/lo smem planes */
#define STAGE_W_HILO(Wh, Wl, NC, LOADEXPR)                                \
    for (int i = tid; i < (NC)*48; i += 512) {                            \
        int c_ = i / 48, k_ = i % 48;                                     \
        float v_ = (LOADEXPR);                                            \
        unsigned h_ = tf32b(v_);                                          \
        (Wh)[c_*WS_G + k_] = __uint_as_float(h_);                         \
        (Wl)[c_*WS_G + k_] = v_ - __uint_as_float(h_);                    \
    }

/* ==== fused 3x GEMM (in_proj / K / Q) on tensor cores, LN fused ====
   TT=64 tokens, K=96 in 2 chunks of 48. 16 warps = 4 ch x 4 tok. */
__global__ void __launch_bounds__(512, 2)
gemm3_tf32(const float* __restrict__ x, const float* __restrict__ Kin,
           const float* __restrict__ Qin, const float* __restrict__ in_w,
           const float* __restrict__ k_w, const float* __restrict__ k_b,
           const float* __restrict__ k_ln_g, const float* __restrict__ k_ln_b,
           const float* __restrict__ q_w, const float* __restrict__ q_b,
           const float* __restrict__ q_ln_g, const float* __restrict__ q_ln_b)
{
    extern __shared__ float sm[];
    float* xs = sm;                      // 96*GT_XS (raw)
    float* wh = sm + 96*GT_XS;           // 192*WS_G
    float* wl = wh + 192*WS_G;           // 192*WS_G
    float* mean_s = wl + 192*WS_G;       // 64
    float* rstd_s = mean_s + 64;         // 64

    int sel = blockIdx.y;
    const float* src  = (sel==0) ? x    : (sel==1 ? Kin : Qin);
    const float* W    = (sel==0) ? in_w : (sel==1 ? k_w : q_w);
    const float* bias = (sel==0) ? 0    : (sel==1 ? k_b : q_b);
    const float* lng  = (sel==1) ? k_ln_g : q_ln_g;
    const float* lnb  = (sel==1) ? k_ln_b : q_ln_b;

    int tid = threadIdx.x, lane = tid & 31, wid = tid >> 5;
    int tok0 = blockIdx.x * GT_TT;
    int b = tok0 / L_, l0 = tok0 % L_;
    const float* srcb = src + ((size_t)b*CDIM)*L_ + l0;

    for (int i = tid; i < CDIM*GT_TT; i += 512) {
        int t = i % GT_TT, k = i / GT_TT;
        xs[k*GT_XS + t] = srcb[(size_t)k*L_ + t];
    }
    __syncthreads();

    if (sel != 0) {
        if (tid < GT_TT) {
            float s = 0.f, ss = 0.f;
            for (int c = 0; c < CDIM; c++) { float v = xs[c*GT_XS + tid]; s += v; ss += v*v; }
            float m = s * (1.0f/CDIM);
            float var = ss * (1.0f/CDIM) - m*m;
            mean_s[tid] = m; rstd_s[tid] = rsqrtf(var + 1e-5f);
        }
        __syncthreads();
        for (int i = tid; i < CDIM*GT_TT; i += 512) {
            int t = i % GT_TT, c = i / GT_TT;
            xs[c*GT_XS + t] = (xs[c*GT_XS + t] - mean_s[t]) * rstd_s[t] * lng[c] + lnb[c];
        }
    }

    int wc = (wid & 3) * 48;
    int wt = (wid >> 2) * 16;

    float acc[3][2][4];
    #pragma unroll
    for (int m = 0; m < 3; m++)
        #pragma unroll
        for (int n = 0; n < 2; n++)
            #pragma unroll
            for (int q = 0; q < 4; q++) acc[m][n][q] = 0.f;

    for (int kc = 0; kc < 2; kc++) {
        __syncthreads();
        STAGE_W_HILO(wh, wl, DM, W[(size_t)c_*CDIM + kc*48 + k_])
        __syncthreads();

        #pragma unroll
        for (int ks = 0; ks < 6; ks++) {
            int kb = ks*8;
            int xk = kc*48 + kb;
            unsigned bh[2][2], bl[2][2];
            #pragma unroll
            for (int n = 0; n < 2; n++) {
                int t = wt + n*8 + (lane>>2);
                BFRAG(bh[n], bl[n], xs, GT_XS, xk, t)
            }
            #pragma unroll
            for (int m = 0; m < 3; m++) {
                unsigned ah[4], al[4];
                AFRAG_S(ah, al, wh, wl, WS_G, wc + m*16 + (lane>>2), kb)
                #pragma unroll
                for (int n = 0; n < 2; n++) {
                    mma8(acc[m][n], ah, bl[n]);
                    mma8(acc[m][n], al, bh[n]);
                    mma8(acc[m][n], ah, bh[n]);
                }
            }
        }
    }

    float* dst = (sel == 0) ? g_xin : ((sel == 1) ? g_kp : g_qp);
    float* dstb = dst + ((size_t)b*DM)*L_ + l0;
    #pragma unroll
    for (int m = 0; m < 3; m++) {
        int c = wc + m*16 + (lane>>2);
        float bv0 = bias ? bias[c] : 0.f;
        float bv1 = bias ? bias[c+8] : 0.f;
        #pragma unroll
        for (int n = 0; n < 2; n++) {
            int t = wt + n*8 + 2*(lane&3);
            float2 v0, v1;
            v0.x = acc[m][n][0] + bv0; v0.y = acc[m][n][1] + bv0;
            v1.x = acc[m][n][2] + bv1; v1.y = acc[m][n][3] + bv1;
            if (sel != 0) { v0.x = siluf(v0.x); v0.y = siluf(v0.y);
                            v1.x = siluf(v1.x); v1.y = siluf(v1.y); }
            *(float2*)&dstb[(size_t)c*L_ + t] = v0;
            *(float2*)&dstb[(size_t)(c+8)*L_ + t] = v1;
        }
    }
}

/* ============ depthwise causal conv (k=4) + silu ============ */
__global__ void __launch_bounds__(256)
conv_silu(const float* __restrict__ cw, const float* __restrict__ cb)
{
    int gid = blockIdx.x * blockDim.x + threadIdx.x;
    if (gid >= B_*DM*L_) return;
    int l  = gid % L_;
    int bd = gid / L_;
    int d  = bd % DM;
    const float* p = g_xin + (size_t)bd*L_ + l;
    float acc = cb[d] + cw[d*4+3] * p[0];
    if (l >= 1) acc = fmaf(cw[d*4+2], p[-1], acc);
    if (l >= 2) acc = fmaf(cw[d*4+1], p[-2], acc);
    if (l >= 3) acc = fmaf(cw[d*4+0], p[-3], acc);
    g_xc[gid] = siluf(acc);
}

/* ============ dtbc (fp32, proven R7 version) ============ */
#define FMA_GROUP16(j)                                                   \
    {   float4 wq = *(const float4*)&wrow[kk];                           \
        acc[0][j] = fmaf(wq.x, xq[0].x, acc[0][j]);                      \
        acc[1][j] = fmaf(wq.x, xq[0].y, acc[1][j]);                      \
        acc[2][j] = fmaf(wq.x, xq[0].z, acc[2][j]);                      \
        acc[3][j] = fmaf(wq.x, xq[0].w, acc[3][j]);                      \
        acc[0][j] = fmaf(wq.y, xq[1].x, acc[0][j]);                      \
        acc[1][j] = fmaf(wq.y, xq[1].y, acc[1][j]);                      \
        acc[2][j] = fmaf(wq.y, xq[1].z, acc[2][j]);                      \
        acc[3][j] = fmaf(wq.y, xq[1].w, acc[3][j]);                      \
        acc[0][j] = fmaf(wq.z, xq[2].x, acc[0][j]);                      \
        acc[1][j] = fmaf(wq.z, xq[2].y, acc[1][j]);                      \
        acc[2][j] = fmaf(wq.z, xq[2].z, acc[2][j]);                      \
        acc[3][j] = fmaf(wq.z, xq[2].w, acc[3][j]);                      \
        acc[0][j] = fmaf(wq.w, xq[3].x, acc[0][j]);                      \
        acc[1][j] = fmaf(wq.w, xq[3].y, acc[1][j]);                      \
        acc[2][j] = fmaf(wq.w, xq[3].z, acc[2][j]);                      \
        acc[3][j] = fmaf(wq.w, xq[3].w, acc[3][j]); }

__global__ void __launch_bounds__(512)
dtbc_kernel(const float* __restrict__ dtbc_w, const float* __restrict__ dt_w,
            const float* __restrict__ dt_b)
{
    extern __shared__ float sm[];
    float* xs   = sm;                    // 96*TTP
    float* ws   = xs + 96*TTP;           // 38*96
    float* dbl  = ws + 38*96;            // 38*TTP
    float* dtw  = dbl + 38*TTP;          // 192*6
    float* dtb  = dtw + 192*6;           // 192
    int tid = threadIdx.x;
    int tok0 = blockIdx.x * TT;
    int b = tok0 / L_, l0 = tok0 % L_;

    for (int i = tid; i < DM*RT; i += 512) dtw[i] = dt_w[i];
    for (int i = tid; i < DM;    i += 512) dtb[i] = dt_b[i];

    int tx = tid & 31, ty = tid >> 5;
    float acc[4][3];
    #pragma unroll
    for (int m = 0; m < 4; m++)
        #pragma unroll
        for (int j = 0; j < 3; j++) acc[m][j] = 0.f;

    for (int kc = 0; kc < 4; kc++) {
        const float* src = (kc < 2) ? g_xc : g_kp;
        int k0 = (kc & 1) * 96;
        __syncthreads();
        for (int i = tid; i < 96*TT; i += 512) {
            int t = i % TT, k = i / TT;
            xs[k*TTP + t] = src[((size_t)b*DM + k0 + k)*L_ + l0 + t];
        }
        for (int i = tid; i < 38*96; i += 512) {
            int c = i / 96, kk = i % 96;
            ws[i] = dtbc_w[c*384 + kc*96 + kk];
        }
        __syncthreads();
        #pragma unroll 2
        for (int kk = 0; kk < 96; kk += 4) {
            float4 xq[4];
            #pragma unroll
            for (int q = 0; q < 4; q++)
                xq[q] = *(const float4*)&xs[(kk+q)*TTP + tx*4];
            #pragma unroll
            for (int j = 0; j < 3; j++) {
                int c = ty + 16*j;
                if (c < 38) {
                    const float* wrow = &ws[c*96];
                    FMA_GROUP16(j)
                }
            }
        }
    }
    __syncthreads();
    #pragma unroll
    for (int j = 0; j < 3; j++) {
        int c = ty + 16*j;
        if (c < 38) {
            float4 v; v.x = acc[0][j]; v.y = acc[1][j]; v.z = acc[2][j]; v.w = acc[3][j];
            *(float4*)&dbl[c*TTP + tx*4] = v;
        }
    }
    __syncthreads();

    for (int i = tid; i < DM*TT; i += 512) {
        int t = i % TT, d = i / TT;
        float s = 2.0f * dtb[d];
        #pragma unroll
        for (int r = 0; r < RT; r++) s = fmaf(dbl[r*TTP + t], dtw[d*RT + r], s);
        float dl = (s > 20.f) ? s : log1pf(__expf(s));
        g_dl[((size_t)b*DM + d)*L_ + l0 + t] = dl;
    }
    for (int i = tid; i < 2*NS*TT; i += 512) {
        int t = i % TT, q = i / TT;
        float v = dbl[(RT + q)*TTP + t];
        if (q < NS) g_Bs[((size_t)b*NS + q)*L_ + l0 + t] = v;
        else        g_Cs[((size_t)b*NS + (q-NS))*L_ + l0 + t] = v;
    }
}

/* ==== gate on tensor cores: z = silu(cat(xc,qp) @ gate_w^T + b) ====
   TT=64 tokens, K=384 in 8 chunks of 48. */
__global__ void __launch_bounds__(512, 2)
gate_tf32(const float* __restrict__ gate_w, const float* __restrict__ gate_b)
{
    extern __shared__ float sm[];
    float* xs = sm;                  // 48*GT_XS (raw)
    float* wh = xs + 48*GT_XS;       // 192*WS_G
    float* wl = wh + 192*WS_G;       // 192*WS_G
    int tid = threadIdx.x, lane = tid & 31, wid = tid >> 5;
    int tok0 = blockIdx.x * GT_TT;
    int b = tok0 / L_, l0 = tok0 % L_;
    int wc = (wid & 3) * 48;
    int wt = (wid >> 2) * 16;

    float acc[3][2][4];
    #pragma unroll
    for (int m = 0; m < 3; m++)
        #pragma unroll
        for (int n = 0; n < 2; n++)
            #pragma unroll
            for (int q = 0; q < 4; q++) acc[m][n][q] = 0.f;

    for (int kc = 0; kc < 8; kc++) {
        const float* src = (kc < 4) ? g_xc : g_qp;
        int ch0 = (kc & 3) * 48;
        __syncthreads();
        for (int i = tid; i < 48*GT_TT; i += 512) {
            int t = i % GT_TT, k = i / GT_TT;
            xs[k*GT_XS + t] = src[((size_t)b*DM + ch0 + k)*L_ + l0 + t];
        }
        STAGE_W_HILO(wh, wl, DM, gate_w[(size_t)c_*384 + kc*48 + k_])
        __syncthreads();

        #pragma unroll
        for (int ks = 0; ks < 6; ks++) {
            int kb = ks*8;
            unsigned bh[2][2], bl[2][2];
            #pragma unroll
            for (int n = 0; n < 2; n++) {
                int t = wt + n*8 + (lane>>2);
                BFRAG(bh[n], bl[n], xs, GT_XS, kb, t)
            }
            #pragma unroll
            for (int m = 0; m < 3; m++) {
                unsigned ah[4], al[4];
                AFRAG_S(ah, al, wh, wl, WS_G, wc + m*16 + (lane>>2), kb)
                #pragma unroll
                for (int n = 0; n < 2; n++) {
                    mma8(acc[m][n], ah, bl[n]);
                    mma8(acc[m][n], al, bh[n]);
                    mma8(acc[m][n], ah, bh[n]);
                }
            }
        }
    }

    float* dstb = g_z + ((size_t)b*DM)*L_ + l0;
    #pragma unroll
    for (int m = 0; m < 3; m++) {
        int c = wc + m*16 + (lane>>2);
        float bv0 = gate_b[c], bv1 = gate_b[c+8];
        #pragma unroll
        for (int n = 0; n < 2; n++) {
            int t = wt + n*8 + 2*(lane&3);
            float2 v0, v1;
            v0.x = siluf(acc[m][n][0] + bv0); v0.y = siluf(acc[m][n][1] + bv0);
            v1.x = siluf(acc[m][n][2] + bv1); v1.y = siluf(acc[m][n][3] + bv1);
            *(float2*)&dstb[(size_t)c*L_ + t] = v0;
            *(float2*)&dstb[(size_t)(c+8)*L_ + t] = v1;
        }
    }
}

/* ============ chunked selective scan (unchanged) ============ */
__global__ void __launch_bounds__(256)
scan1(const float* __restrict__ A_log)
{
    __shared__ float dls[16*97], xcs[16*97], bs[16*97];
    int b = blockIdx.z, ch = blockIdx.y, dblk = blockIdx.x;
    int d0 = dblk*16;
    int tid = threadIdx.x;
    for (int i = tid; i < 16*G_; i += 256) {
        int r = i / G_, t = i % G_;
        dls[r*97+t] = g_dl[((size_t)b*DM + d0 + r)*L_ + ch*G_ + t];
        xcs[r*97+t] = g_xc[((size_t)b*DM + d0 + r)*L_ + ch*G_ + t];
        bs [r*97+t] = g_Bs[((size_t)b*NS + r)*L_ + ch*G_ + t];
    }
    __syncthreads();
    int n = tid & 15, dloc = tid >> 4;
    int d = d0 + dloc;
    float A = -__expf(A_log[d*NS + n]);
    float h = 0.f, S = 0.f;
    #pragma unroll 4
    for (int t = 0; t < G_; t++) {
        float dl = dls[dloc*97+t];
        float a = __expf(dl * A);
        S += dl;
        h = fmaf(a, h, dl * xcs[dloc*97+t] * bs[n*97+t]);
    }
    size_t o = (((size_t)(b*NCH + ch))*DM + d)*NS + n;
    g_P[o] = __expf(A * S); g_Hl[o] = h;
}

__global__ void __launch_bounds__(256)
scan2()
{
    int idx = blockIdx.x * blockDim.x + threadIdx.x;
    if (idx >= B_*DM*NS) return;
    int b = idx / (DM*NS);
    int dn = idx % (DM*NS);
    float h = 0.f;
    for (int ch = 0; ch < NCH; ch++) {
        size_t o = ((size_t)(b*NCH + ch))*(DM*NS) + dn;
        g_Hi[o] = h;
        h = fmaf(g_P[o], h, g_Hl[o]);
    }
}

__global__ void __launch_bounds__(256)
scan3(const float* __restrict__ A_log, const float* __restrict__ Dp)
{
    __shared__ float dls[16*97], xcs[16*97], bs[16*97], cs[16*97], zs[16*97], ys[16*97];
    int b = blockIdx.z, ch = blockIdx.y, dblk = blockIdx.x;
    int d0 = dblk*16;
    int tid = threadIdx.x;
    for (int i = tid; i < 16*G_; i += 256) {
        int r = i / G_, t = i % G_;
        size_t db = ((size_t)b*DM + d0 + r)*L_ + ch*G_ + t;
        size_t nb = ((size_t)b*NS + r)*L_ + ch*G_ + t;
        dls[r*97+t] = g_dl[db];
        xcs[r*97+t] = g_xc[db];
        zs [r*97+t] = g_z [db];
        bs [r*97+t] = g_Bs[nb];
        cs [r*97+t] = g_Cs[nb];
    }
    __syncthreads();
    int n = tid & 15, dloc = tid >> 4;
    int d = d0 + dloc;
    float A = -__expf(A_log[d*NS + n]);
    size_t o = (((size_t)(b*NCH + ch))*DM + d)*NS + n;
    float h = g_Hi[o];
    float Dd = Dp[d];
    for (int t = 0; t < G_; t++) {
        float dl = dls[dloc*97+t];
        float u  = xcs[dloc*97+t];
        float a = __expf(dl * A);
        h = fmaf(a, h, dl * u * bs[n*97+t]);
        float v = h * cs[n*97+t];
        v += __shfl_xor_sync(0xffffffffu, v, 1);
        v += __shfl_xor_sync(0xffffffffu, v, 2);
        v += __shfl_xor_sync(0xffffffffu, v, 4);
        v += __shfl_xor_sync(0xffffffffu, v, 8);
        if (n == 0)
            ys[dloc*97+t] = (v + u * Dd) * zs[dloc*97+t];
    }
    __syncthreads();
    for (int i = tid; i < 16*G_; i += 256) {
        int r = i / G_, t = i % G_;
        g_y[((size_t)b*DM + d0 + r)*L_ + ch*G_ + t] = ys[r*97+t];
    }
}

/* ==== out projection on tensor cores: out = y @ out_w^T ====
   TT=128 tokens, N=96, K=192 in 4 chunks of 48. 16 warps = 2 ch x 8 tok. */
__global__ void __launch_bounds__(512, 2)
gemm_out_tf32(const float* __restrict__ out_w, float* __restrict__ out)
{
    extern __shared__ float sm[];
    float* xs = sm;                  // 48*OT_XS (raw)
    float* wh = xs + 48*OT_XS;       // 96*WS_G
    float* wl = wh + 96*WS_G;        // 96*WS_G
    int tid = threadIdx.x, lane = tid & 31, wid = tid >> 5;
    int tok0 = blockIdx.x * TT;
    int b = tok0 / L_, l0 = tok0 % L_;
    int wc = (wid & 1) * 48;
    int wt = (wid >> 1) * 16;

    float acc[3][2][4];
    #pragma unroll
    for (int m = 0; m < 3; m++)
        #pragma unroll
        for (int n = 0; n < 2; n++)
            #pragma unroll
            for (int q = 0; q < 4; q++) acc[m][n][q] = 0.f;

    for (int kc = 0; kc < 4; kc++) {
        __syncthreads();
        for (int i = tid; i < 48*TT; i += 512) {
            int t = i % TT, k = i / TT;
            xs[k*OT_XS + t] = g_y[((size_t)b*DM + kc*48 + k)*L_ + l0 + t];
        }
        STAGE_W_HILO(wh, wl, CDIM, out_w[(size_t)c_*DM + kc*48 + k_])
        __syncthreads();

        #pragma unroll
        for (int ks = 0; ks < 6; ks++) {
            int kb = ks*8;
            unsigned bh[2][2], bl[2][2];
            #pragma unroll
            for (int n = 0; n < 2; n++) {
                int t = wt + n*8 + (lane>>2);
                BFRAG(bh[n], bl[n], xs, OT_XS, kb, t)
            }
            #pragma unroll
            for (int m = 0; m < 3; m++) {
                unsigned ah[4], al[4];
                AFRAG_S(ah, al, wh, wl, WS_G, wc + m*16 + (lane>>2), kb)
                #pragma unroll
                for (int n = 0; n < 2; n++) {
                    mma8(acc[m][n], ah, bl[n]);
                    mma8(acc[m][n], al, bh[n]);
                    mma8(acc[m][n], ah, bh[n]);
                }
            }
        }
    }

    float* ob = out + ((size_t)b*CDIM)*L_ + l0;
    #pragma unroll
    for (int m = 0; m < 3; m++) {
        int c = wc + m*16 + (lane>>2);
        #pragma unroll
        for (int n = 0; n < 2; n++) {
            int t = wt + n*8 + 2*(lane&3);
            float2 v0, v1;
            v0.x = acc[m][n][0]; v0.y = acc[m][n][1];
            v1.x = acc[m][n][2]; v1.y = acc[m][n][3];
            *(float2*)&ob[(size_t)c*L_ + t] = v0;
            *(float2*)&ob[(size_t)(c+8)*L_ + t] = v1;
        }
    }
}

/* ============ host launcher ============ */
extern "C" void kernel_launch(void* const* d_in, const int* in_sizes, int n_in,
                              void* d_out, int out_size)
{
    const float* x         = (const float*)d_in[0];
    const float* Kin       = (const float*)d_in[1];
    const float* Qin       = (const float*)d_in[2];
    const float* in_proj_w = (const float*)d_in[3];
    const float* conv_w    = (const float*)d_in[4];
    const float* conv_b    = (const float*)d_in[5];
    const float* k_ln_g    = (const float*)d_in[6];
    const float* k_ln_b    = (const float*)d_in[7];
    const float* k_w       = (const float*)d_in[8];
    const float* k_b       = (const float*)d_in[9];
    const float* q_ln_g    = (const float*)d_in[10];
    const float* q_ln_b    = (const float*)d_in[11];
    const float* q_w       = (const float*)d_in[12];
    const float* q_b       = (const float*)d_in[13];
    const float* dtbc_w    = (const float*)d_in[14];
    const float* dt_w      = (const float*)d_in[15];
    const float* dt_b      = (const float*)d_in[16];
    const float* gate_w    = (const float*)d_in[17];
    const float* gate_b    = (const float*)d_in[18];
    const float* A_log     = (const float*)d_in[19];
    const float* Dp        = (const float*)d_in[20];
    const float* out_w     = (const float*)d_in[21];
    float* out = (float*)d_out;

    const int SMEM_G3 = (96*GT_XS + 2*192*WS_G + 128) * 4;   /* ~106 KB */
    const int SMEM_D  = (96*TTP + 38*96 + 38*TTP + 192*6 + 192) * 4;  /* ~89 KB */
    const int SMEM_GT = (48*GT_XS + 2*192*WS_G) * 4;         /* ~92 KB */
    const int SMEM_OT = (48*OT_XS + 2*96*WS_G) * 4;          /* ~65 KB */

    cudaFuncSetAttribute(gemm3_tf32,    cudaFuncAttributeMaxDynamicSharedMemorySize, SMEM_G3);
    cudaFuncSetAttribute(dtbc_kernel,   cudaFuncAttributeMaxDynamicSharedMemorySize, SMEM_D);
    cudaFuncSetAttribute(gate_tf32,     cudaFuncAttributeMaxDynamicSharedMemorySize, SMEM_GT);
    cudaFuncSetAttribute(gemm_out_tf32, cudaFuncAttributeMaxDynamicSharedMemorySize, SMEM_OT);

    /* 1. fused in_proj + K + Q (tensor cores, LN fused) */
    gemm3_tf32<<<dim3(BL/GT_TT,3), 512, SMEM_G3>>>(x, Kin, Qin, in_proj_w,
        k_w, k_b, k_ln_g, k_ln_b, q_w, q_b, q_ln_g, q_ln_b);
    /* 2. depthwise conv + silu */
    conv_silu<<<(B_*DM*L_)/256, 256>>>(conv_w, conv_b);
    /* 3. dtbc -> delta, B, C (fp32) */
    dtbc_kernel<<<NTILE, 512, SMEM_D>>>(dtbc_w, dt_w, dt_b);
    /* 4. gate -> silu(z) (tensor cores) */
    gate_tf32<<<BL/GT_TT, 512, SMEM_GT>>>(gate_w, gate_b);
    /* 5-7. chunked selective scan */
    scan1<<<dim3(DM/16, NCH, B_), 256>>>(A_log);
    scan2<<<(B_*DM*NS)/256, 256>>>();
    scan3<<<dim3(DM/16, NCH, B_), 256>>>(A_log, Dp);
    /* 8. output projection (tensor cores) */
    gemm_out_tf32<<<NTILE, 512, SMEM_OT>>>(out_w, out);
}